// round 11
// baseline (speedup 1.0000x reference)
#include <cuda_runtime.h>
#include <cuda_fp16.h>
#include <cstdint>

#define N_NODES 100000
#define N_EDGES 3200000
#define HID 256
#define EMB 128
#define N_PAIRS 100000

// ===================== scratch (device globals) =============================
__device__ __half g_xh [N_NODES * HID];         // spmm1 input (fp16)
__device__ __half g_axh[N_NODES * HID];         // spmm1 out = GEMM1 A (fp16)
__device__ __half g_hh [N_NODES * HID];         // GEMM1 out = GEMM2 A (fp16)
__device__ __half g_hwh[N_NODES * EMB];         // GEMM2 out (fp16, feeds spmm2)
__device__ float  g_z  [N_NODES * EMB];         // spmm2 out (fp32)
__device__ int    g_rowptr[N_NODES + 1];
// transposed + fp16-split weights: [N][K]
__device__ __half g_w1hi[HID * HID],      g_w1lo[HID * HID];
__device__ __half g_w2hi[EMB * HID],      g_w2lo[EMB * HID];
__device__ __half g_wp1hi[EMB * 3 * EMB], g_wp1lo[EMB * 3 * EMB];

// ===================== helpers ==============================================
__device__ __forceinline__ uint32_t smem_u32(const void* p) {
    uint32_t a;
    asm("{ .reg .u64 t; cvta.to.shared.u64 t, %1; cvt.u32.u64 %0, t; }"
        : "=r"(a) : "l"(p));
    return a;
}
__device__ __forceinline__ void cp16(uint32_t dst, const void* src) {
    asm volatile("cp.async.cg.shared.global [%0], [%1], 16;" :: "r"(dst), "l"(src));
}
#define CP_COMMIT() asm volatile("cp.async.commit_group;" ::: "memory")
#define CP_WAIT1()  asm volatile("cp.async.wait_group 1;" ::: "memory")

__device__ __forceinline__ void ldsm4(uint32_t& r0, uint32_t& r1,
                                      uint32_t& r2, uint32_t& r3, uint32_t addr) {
    asm volatile("ldmatrix.sync.aligned.m8n8.x4.shared.b16 {%0,%1,%2,%3}, [%4];"
                 : "=r"(r0), "=r"(r1), "=r"(r2), "=r"(r3) : "r"(addr));
}
__device__ __forceinline__ void mma_h(float& d0, float& d1, float& d2, float& d3,
                                      uint32_t a0, uint32_t a1, uint32_t a2, uint32_t a3,
                                      uint32_t b0, uint32_t b1) {
    asm volatile(
        "mma.sync.aligned.m16n8k16.row.col.f32.f16.f16.f32 "
        "{%0,%1,%2,%3}, {%4,%5,%6,%7}, {%8,%9}, {%0,%1,%2,%3};"
        : "+f"(d0), "+f"(d1), "+f"(d2), "+f"(d3)
        : "r"(a0), "r"(a1), "r"(a2), "r"(a3), "r"(b0), "r"(b1));
}
__device__ __forceinline__ void split_h(float v, __half& h, __half& l) {
    h = __float2half(v);
    l = __float2half(v - __half2float(h));
}
__device__ __forceinline__ float2 h2f2(uint32_t u) {
    return __half22float2(*reinterpret_cast<__half2*>(&u));
}
__device__ __forceinline__ uint32_t pkh2(float a, float b) {
    __half2 t = __floats2half2_rn(a, b);
    return *reinterpret_cast<uint32_t*>(&t);
}

// ===================== small kernels ========================================
// rowptr via edge-boundary scatter (rows sorted ascending)
__global__ void build_rowptr(const int* __restrict__ rows) {
    int e = blockIdx.x * blockDim.x + threadIdx.x;
    if (e >= N_EDGES) return;
    int r  = rows[e];
    int rn = (e + 1 < N_EDGES) ? rows[e + 1] : N_NODES;
    if (e == 0)
        for (int n = 0; n <= r; n++) g_rowptr[n] = 0;
    for (int n = r + 1; n <= rn; n++) g_rowptr[n] = e + 1;
}

// x = fp16(node_emb + type_emb[type])
__global__ void add_emb(const float* __restrict__ node_emb,
                        const float* __restrict__ type_emb,
                        const int* __restrict__ tids) {
    int i = blockIdx.x * blockDim.x + threadIdx.x;          // float4 index
    const int NV = N_NODES * HID / 4;
    if (i >= NV) return;
    int n  = i / (HID / 4);
    int k4 = i % (HID / 4);
    int t  = tids[n];
    float4 a = reinterpret_cast<const float4*>(node_emb)[i];
    float4 b = reinterpret_cast<const float4*>(type_emb)[t * (HID / 4) + k4];
    reinterpret_cast<uint2*>(g_xh)[i] =
        make_uint2(pkh2(a.x + b.x, a.y + b.y), pkh2(a.z + b.z, a.w + b.w));
}

// all 3 weights: W [K,N] fp32 -> Wt_hi/Wt_lo [N,K] fp16 split, one launch
__global__ void prep_w_all(const float* __restrict__ W1, const float* __restrict__ W2,
                           const float* __restrict__ Wp1) {
    int i = blockIdx.x * blockDim.x + threadIdx.x;
    const int S1 = HID * HID;
    const int S2 = S1 + HID * EMB;
    const int S3 = S2 + 3 * EMB * EMB;
    const float* W; __half *hi, *lo; int K, N, j;
    if (i < S1)      { W = W1;  hi = g_w1hi;  lo = g_w1lo;  K = HID;     N = HID; j = i; }
    else if (i < S2) { W = W2;  hi = g_w2hi;  lo = g_w2lo;  K = HID;     N = EMB; j = i - S1; }
    else if (i < S3) { W = Wp1; hi = g_wp1hi; lo = g_wp1lo; K = 3 * EMB; N = EMB; j = i - S2; }
    else return;
    int k = j / N, n = j % N;
    __half h, l;
    split_h(W[j], h, l);
    hi[n * K + k] = h;
    lo[n * K + k] = l;
}

// out[p] = bp2  (pre-init for GEMM3's fused dot epilogue)
__global__ void init_out(float* __restrict__ out, const float* __restrict__ bp2) {
    int i = blockIdx.x * blockDim.x + threadIdx.x;
    if (i < N_PAIRS) out[i] = bp2[0];
}

// ---------------- SpMM: warp-per-node, wide gathers, shuffle indices --------
// All edge groups (incl. remainder) run the SAME unrolled loop with c=0,v=0
// padding: 0*x[0] = +0 adds exactly nothing, order of real edges unchanged.
// H=256: lane gathers uint4 (8 halves), unroll 4. H=128: uint2, unroll 8.
// OUT: 0 = fp32 (+bias), 2 = fp16.
template <int H, int OUT>
__global__ void __launch_bounds__(256, 6)
spmm_warp(const __half* __restrict__ x,
          float* __restrict__ yf,
          __half* __restrict__ yh,
          const int* __restrict__ cols,
          const float* __restrict__ vals,
          const float* __restrict__ bias) {
    constexpr int PER = H / 32;     // halves per lane (8 or 4)
    constexpr int UNR = (PER == 8) ? 4 : 8;
    const int lane = threadIdx.x & 31;
    const int n = blockIdx.x * 8 + (threadIdx.x >> 5);
    if (n >= N_NODES) return;

    int e  = g_rowptr[n];
    const int e1 = g_rowptr[n + 1];

    float acc[PER];
#pragma unroll
    for (int k = 0; k < PER; k++) acc[k] = 0.f;

    // 32-edge groups with zero padding: uniform MLP-batched path
    for (; e < e1; e += 32) {
        int   c = 0;
        float v = 0.f;
        if (e + lane < e1) {
            c = __ldg(cols + e + lane);
            v = __ldg(vals + e + lane);
        }
#pragma unroll UNR
        for (int j = 0; j < 32; j++) {
            int   cj = __shfl_sync(0xffffffffu, c, j);
            float vj = __shfl_sync(0xffffffffu, v, j);
            if (PER == 8) {
                uint4 q = __ldg(reinterpret_cast<const uint4*>(x) +
                                (size_t)cj * (H / 8) + lane);
                float2 f0 = h2f2(q.x), f1 = h2f2(q.y), f2 = h2f2(q.z), f3 = h2f2(q.w);
                acc[0] += vj * f0.x; acc[1] += vj * f0.y;
                acc[2] += vj * f1.x; acc[3] += vj * f1.y;
                acc[4 % PER] += vj * f2.x; acc[5 % PER] += vj * f2.y;
                acc[6 % PER] += vj * f3.x; acc[7 % PER] += vj * f3.y;
            } else {
                uint2 q = __ldg(reinterpret_cast<const uint2*>(x) +
                                (size_t)cj * (H / 4) + lane);
                float2 f0 = h2f2(q.x), f1 = h2f2(q.y);
                acc[0] += vj * f0.x; acc[1] += vj * f0.y;
                acc[2 % PER] += vj * f1.x; acc[3 % PER] += vj * f1.y;
            }
        }
    }

    if (OUT == 0) {
#pragma unroll
        for (int k = 0; k < PER; k++)
            if (bias) acc[k] += __ldg(bias + lane * PER + k);
#pragma unroll
        for (int k = 0; k < PER; k += 4) {
            float4 o = make_float4(acc[k], acc[k + 1],
                                   acc[(k + 2) % PER], acc[(k + 3) % PER]);
            *reinterpret_cast<float4*>(yf + (size_t)n * H + lane * PER + k) = o;
        }
    } else {
        uint32_t p[PER / 2];
#pragma unroll
        for (int k = 0; k < PER / 2; k++)
            p[k] = pkh2(acc[2 * k], acc[2 * k + 1]);
        if (PER == 8) {
            uint4 o = make_uint4(p[0], p[1], p[2 % (PER / 2)], p[3 % (PER / 2)]);
            *reinterpret_cast<uint4*>(yh + (size_t)n * H + lane * 8) = o;
        } else {
            uint2 o = make_uint2(p[0], p[1 % (PER / 2)]);
            *reinterpret_cast<uint2*>(yh + (size_t)n * H + lane * 4) = o;
        }
    }
}

// ===================== HMMA GEMM (fp16 A x fp16-split W, 2 products) ========
// C[M, NTOT] = A[M, KTOT] @ W^T  (W fp16 hi/lo, shape [NTOT, KTOT])
// CTA tile 128(M) x 128(N), 8 warps 4x2, warp tile 32x64, kc=32, 2-stage.
// MODE 1: A from Ah_ (fp16); bias+relu fp16 out.
// MODE 3: A from Ah_ (fp16); fp16 out.
// MODE 4: FUSED FEAT — A built on the fly from z fp32 via pairs
//         (seg = chunk/4: 0=z[s], 1=z[d], 2=z[s]*z[d]); bias+relu,
//         dot Wp2v, atomicAdd into Cf (pre-initialized with bp2).
template <int KTOT, int NTOT, int MODE>
__global__ void __launch_bounds__(256, 2)
gemm_mma(const __half* __restrict__ Ah_,
         const __half* __restrict__ Whi,
         const __half* __restrict__ Wlo,
         float* __restrict__ Cf,
         __half* __restrict__ Ch,
         const float* __restrict__ bias,
         const float* __restrict__ Wp2v,
         const float* __restrict__ zf,
         const int* __restrict__ pairs, int M) {
    constexpr int KC = 32;
    constexpr int NS = KTOT / KC;
    constexpr int ST_A  = 0;
    constexpr int ST_WH = 8192;
    constexpr int ST_WL = 16384;
    constexpr int STAGE = 24576;

    extern __shared__ __align__(128) char smem[];
    const uint32_t sb = smem_u32(smem);

    const int tid  = threadIdx.x;
    const int lane = tid & 31;
    const int wm   = (tid >> 5) & 3;
    const int wn   = tid >> 7;
    const int m0   = blockIdx.x * 128;
    const int n0   = blockIdx.y * 128;

    auto load_stage = [&](int ks) {
        const int k0 = ks * KC;
        const uint32_t base = sb + (uint32_t)(ks & 1) * STAGE;
#pragma unroll
        for (int i = 0; i < 2; i++) {
            int id  = tid + i * 256;
            int row = id >> 2;
            int c   = id & 3;
            uint32_t soff = (uint32_t)(row * 64 + ((c ^ ((row >> 1) & 3)) << 4));
            if (MODE == 4) {
                int p = min(m0 + row, M - 1);
                int seg  = ks >> 2;
                int kloc = (ks & 3) * KC + c * 8;
                int s = __ldg(pairs + p);
                int d = __ldg(pairs + N_PAIRS + p);
                uint4 o;
                if (seg == 0) {
                    const float* zp = zf + (size_t)s * EMB + kloc;
                    float4 a0 = *reinterpret_cast<const float4*>(zp);
                    float4 a1 = *reinterpret_cast<const float4*>(zp + 4);
                    o = make_uint4(pkh2(a0.x, a0.y), pkh2(a0.z, a0.w),
                                   pkh2(a1.x, a1.y), pkh2(a1.z, a1.w));
                } else if (seg == 1) {
                    const float* zp = zf + (size_t)d * EMB + kloc;
                    float4 a0 = *reinterpret_cast<const float4*>(zp);
                    float4 a1 = *reinterpret_cast<const float4*>(zp + 4);
                    o = make_uint4(pkh2(a0.x, a0.y), pkh2(a0.z, a0.w),
                                   pkh2(a1.x, a1.y), pkh2(a1.z, a1.w));
                } else {
                    const float* zs = zf + (size_t)s * EMB + kloc;
                    const float* zd = zf + (size_t)d * EMB + kloc;
                    float4 a0 = *reinterpret_cast<const float4*>(zs);
                    float4 a1 = *reinterpret_cast<const float4*>(zs + 4);
                    float4 b0 = *reinterpret_cast<const float4*>(zd);
                    float4 b1 = *reinterpret_cast<const float4*>(zd + 4);
                    o = make_uint4(pkh2(a0.x * b0.x, a0.y * b0.y),
                                   pkh2(a0.z * b0.z, a0.w * b0.w),
                                   pkh2(a1.x * b1.x, a1.y * b1.y),
                                   pkh2(a1.z * b1.z, a1.w * b1.w));
                }
                *reinterpret_cast<uint4*>(smem + ((ks & 1) ? STAGE : 0) + ST_A + soff) = o;
            } else {
                int rowa = min(m0 + row, M - 1);
                cp16(base + ST_A + soff, Ah_ + (size_t)rowa * KTOT + k0 + c * 8);
            }
            size_t goff = (size_t)(n0 + row) * KTOT + k0 + c * 8;
            cp16(base + ST_WH + soff, Whi + goff);
            cp16(base + ST_WL + soff, Wlo + goff);
        }
    };

    float acc[2][8][4];
#pragma unroll
    for (int a = 0; a < 2; a++)
#pragma unroll
        for (int b = 0; b < 8; b++)
#pragma unroll
            for (int c = 0; c < 4; c++) acc[a][b][c] = 0.f;

    const int lrow  = (lane & 7) + ((lane >> 3) & 1) * 8;
    const int khalf = lane >> 4;

    load_stage(0);
    CP_COMMIT();
    if (MODE == 4) __syncthreads();

    for (int ks = 0; ks < NS; ks++) {
        if (ks + 1 < NS) load_stage(ks + 1);
        CP_COMMIT();
        CP_WAIT1();
        __syncthreads();

        const uint32_t base = sb + (uint32_t)(ks & 1) * STAGE;
#pragma unroll
        for (int kk = 0; kk < 2; kk++) {
            const int c = kk * 2 + khalf;
            uint32_t ah[2][4];
#pragma unroll
            for (int mi = 0; mi < 2; mi++) {
                int row = wm * 32 + mi * 16 + lrow;
                uint32_t off = (uint32_t)(row * 64 + ((c ^ ((row >> 1) & 3)) << 4));
                ldsm4(ah[mi][0], ah[mi][1], ah[mi][2], ah[mi][3], base + ST_A + off);
            }
            uint32_t bh[4][4], bl[4][4];
#pragma unroll
            for (int ng = 0; ng < 4; ng++) {
                int row = wn * 64 + ng * 16 + lrow;
                uint32_t off = (uint32_t)(row * 64 + ((c ^ ((row >> 1) & 3)) << 4));
                ldsm4(bh[ng][0], bh[ng][1], bh[ng][2], bh[ng][3], base + ST_WH + off);
                ldsm4(bl[ng][0], bl[ng][1], bl[ng][2], bl[ng][3], base + ST_WL + off);
            }
#pragma unroll
            for (int mi = 0; mi < 2; mi++)
#pragma unroll
                for (int ng = 0; ng < 4; ng++)
#pragma unroll
                    for (int sub = 0; sub < 2; sub++) {
                        int ni = ng * 2 + sub;
                        float* d = acc[mi][ni];
                        mma_h(d[0], d[1], d[2], d[3],
                              ah[mi][0], ah[mi][1], ah[mi][2], ah[mi][3],
                              bh[ng][sub], bh[ng][sub + 2]);
                        mma_h(d[0], d[1], d[2], d[3],
                              ah[mi][0], ah[mi][1], ah[mi][2], ah[mi][3],
                              bl[ng][sub], bl[ng][sub + 2]);
                    }
        }
        __syncthreads();
    }

    // ---- epilogue ----
    if (MODE == 4) {
#pragma unroll
        for (int mi = 0; mi < 2; mi++) {
            float s0 = 0.f, s1 = 0.f;
#pragma unroll
            for (int ni = 0; ni < 8; ni++) {
                int col = n0 + wn * 64 + ni * 8 + 2 * (lane & 3);
                float b0 = __ldg(bias + col),  b1 = __ldg(bias + col + 1);
                float w0 = __ldg(Wp2v + col),  w1 = __ldg(Wp2v + col + 1);
                s0 += fmaxf(acc[mi][ni][0] + b0, 0.f) * w0
                    + fmaxf(acc[mi][ni][1] + b1, 0.f) * w1;
                s1 += fmaxf(acc[mi][ni][2] + b0, 0.f) * w0
                    + fmaxf(acc[mi][ni][3] + b1, 0.f) * w1;
            }
            s0 += __shfl_xor_sync(0xffffffffu, s0, 1);
            s0 += __shfl_xor_sync(0xffffffffu, s0, 2);
            s1 += __shfl_xor_sync(0xffffffffu, s1, 1);
            s1 += __shfl_xor_sync(0xffffffffu, s1, 2);
            if ((lane & 3) == 0) {
                int r0 = m0 + wm * 32 + mi * 16 + (lane >> 2);
                int r1 = r0 + 8;
                if (r0 < M) atomicAdd(Cf + r0, s0);
                if (r1 < M) atomicAdd(Cf + r1, s1);
            }
        }
        return;
    }
#pragma unroll
    for (int mi = 0; mi < 2; mi++) {
        int r0 = m0 + wm * 32 + mi * 16 + (lane >> 2);
        int r1 = r0 + 8;
#pragma unroll
        for (int ni = 0; ni < 8; ni++) {
            int col = n0 + wn * 64 + ni * 8 + 2 * (lane & 3);
            float v0 = acc[mi][ni][0], v1 = acc[mi][ni][1];
            float v2 = acc[mi][ni][2], v3 = acc[mi][ni][3];
            if (MODE == 1) {
                float b0 = __ldg(bias + col), b1 = __ldg(bias + col + 1);
                v0 = fmaxf(v0 + b0, 0.f); v1 = fmaxf(v1 + b1, 0.f);
                v2 = fmaxf(v2 + b0, 0.f); v3 = fmaxf(v3 + b1, 0.f);
            }
            if (r0 < M)
                *reinterpret_cast<uint32_t*>(Ch + (size_t)r0 * NTOT + col) = pkh2(v0, v1);
            if (r1 < M)
                *reinterpret_cast<uint32_t*>(Ch + (size_t)r1 * NTOT + col) = pkh2(v2, v3);
        }
    }
}

// ===========================================================================
extern "C" void kernel_launch(void* const* d_in, const int* in_sizes, int n_in,
                              void* d_out, int out_size) {
    const int*   tids     = (const int*)  d_in[0];
    const int*   rows     = (const int*)  d_in[1];
    const int*   cols     = (const int*)  d_in[2];
    const float* vals     = (const float*)d_in[3];
    const int*   pairs    = (const int*)  d_in[4];
    const float* node_emb = (const float*)d_in[5];
    const float* type_emb = (const float*)d_in[6];
    const float* W1  = (const float*)d_in[7];
    const float* b1  = (const float*)d_in[8];
    const float* W2  = (const float*)d_in[9];
    const float* b2  = (const float*)d_in[10];
    const float* Wp1 = (const float*)d_in[11];
    const float* bp1 = (const float*)d_in[12];
    const float* Wp2 = (const float*)d_in[13];
    const float* bp2 = (const float*)d_in[14];
    float* out = (float*)d_out;

    void *pxh, *paxh, *phh, *phwh, *pz;
    void *w1h, *w1l, *w2h, *w2l, *wp1h, *wp1l;
    cudaGetSymbolAddress(&pxh,  g_xh);
    cudaGetSymbolAddress(&paxh, g_axh);
    cudaGetSymbolAddress(&phh,  g_hh);
    cudaGetSymbolAddress(&phwh, g_hwh);
    cudaGetSymbolAddress(&pz,   g_z);
    cudaGetSymbolAddress(&w1h,  g_w1hi);  cudaGetSymbolAddress(&w1l, g_w1lo);
    cudaGetSymbolAddress(&w2h,  g_w2hi);  cudaGetSymbolAddress(&w2l, g_w2lo);
    cudaGetSymbolAddress(&wp1h, g_wp1hi); cudaGetSymbolAddress(&wp1l, g_wp1lo);

    constexpr int SMEM = 2 * 24576;   // 48 KB
    cudaFuncSetAttribute(gemm_mma<256, 256, 1>,
                         cudaFuncAttributeMaxDynamicSharedMemorySize, SMEM);
    cudaFuncSetAttribute(gemm_mma<256, 128, 3>,
                         cudaFuncAttributeMaxDynamicSharedMemorySize, SMEM);
    cudaFuncSetAttribute(gemm_mma<384, 128, 4>,
                         cudaFuncAttributeMaxDynamicSharedMemorySize, SMEM);

    // 0. weight prep (one launch, transpose + fp16 split)
    {
        int tot = HID * HID + HID * EMB + 3 * EMB * EMB;
        prep_w_all<<<(tot + 255) / 256, 256>>>(W1, W2, Wp1);
    }
    // 1. row_ptr (edge-boundary scatter)
    build_rowptr<<<(N_EDGES + 255) / 256, 256>>>(rows);
    // 2. x = fp16(node_emb + type_emb[type])
    add_emb<<<(N_NODES * HID / 4 + 255) / 256, 256>>>(node_emb, type_emb, tids);
    // 3. ax = spmm(x) -> fp16   [warp-per-node, padded batches]
    spmm_warp<HID, 2><<<(N_NODES + 7) / 8, 256>>>(
        (const __half*)pxh, nullptr, (__half*)paxh, cols, vals, nullptr);
    // 4. h = relu(ax @ W1 + b1) -> fp16   [HMMA 128x128]
    {
        dim3 grid((N_NODES + 127) / 128, HID / 128);
        gemm_mma<256, 256, 1><<<grid, 256, SMEM>>>(
            (const __half*)paxh, (const __half*)w1h, (const __half*)w1l,
            nullptr, (__half*)phh, b1, nullptr, nullptr, nullptr, N_NODES);
    }
    // 5. hw = h @ W2 -> fp16   [HMMA 128x128]
    {
        dim3 grid((N_NODES + 127) / 128, EMB / 128);
        gemm_mma<256, 128, 3><<<grid, 256, SMEM>>>(
            (const __half*)phh, (const __half*)w2h, (const __half*)w2l,
            nullptr, (__half*)phwh, nullptr, nullptr, nullptr, nullptr, N_NODES);
    }
    // 6. z = spmm(hw) + b2  (fp32)   [warp-per-node, padded batches]
    spmm_warp<EMB, 0><<<(N_NODES + 7) / 8, 256>>>(
        (const __half*)phwh, (float*)pz, nullptr, cols, vals, b2);
    // 7+8. out = relu(feat @ Wp1 + bp1) @ Wp2 + bp2  [fused feat + HMMA + dot]
    init_out<<<(N_PAIRS + 255) / 256, 256>>>(out, bp2);
    {
        dim3 grid((N_PAIRS + 127) / 128, EMB / 128);
        gemm_mma<384, 128, 4><<<grid, 256, SMEM>>>(
            nullptr, (const __half*)wp1h, (const __half*)wp1l,
            out, nullptr, bp1, Wp2, (const float*)pz, pairs, N_PAIRS);
    }
}

// round 12
// speedup vs baseline: 1.0021x; 1.0021x over previous
#include <cuda_runtime.h>
#include <cuda_fp16.h>
#include <cstdint>

#define N_NODES 100000
#define N_EDGES 3200000
#define HID 256
#define EMB 128
#define N_PAIRS 100000

// ===================== scratch (device globals) =============================
__device__ __half g_xh [N_NODES * HID];         // spmm1 input (fp16)
__device__ __half g_axh[N_NODES * HID];         // spmm1 out = GEMM1 A (fp16)
__device__ __half g_hh [N_NODES * HID];         // GEMM1 out = GEMM2 A (fp16)
__device__ __half g_hwh[N_NODES * EMB];         // GEMM2 out (fp16, feeds spmm2)
__device__ float  g_z  [N_NODES * EMB];         // spmm2 out (fp32)
__device__ int    g_rowptr[N_NODES + 1];
// transposed + fp16-split weights: [N][K]
__device__ __half g_w1hi[HID * HID],      g_w1lo[HID * HID];
__device__ __half g_w2hi[EMB * HID],      g_w2lo[EMB * HID];
__device__ __half g_wp1hi[EMB * 3 * EMB], g_wp1lo[EMB * 3 * EMB];

// ===================== helpers ==============================================
__device__ __forceinline__ uint32_t smem_u32(const void* p) {
    uint32_t a;
    asm("{ .reg .u64 t; cvta.to.shared.u64 t, %1; cvt.u32.u64 %0, t; }"
        : "=r"(a) : "l"(p));
    return a;
}
__device__ __forceinline__ void cp16(uint32_t dst, const void* src) {
    asm volatile("cp.async.cg.shared.global [%0], [%1], 16;" :: "r"(dst), "l"(src));
}
#define CP_COMMIT() asm volatile("cp.async.commit_group;" ::: "memory")
#define CP_WAIT1()  asm volatile("cp.async.wait_group 1;" ::: "memory")

__device__ __forceinline__ void ldsm4(uint32_t& r0, uint32_t& r1,
                                      uint32_t& r2, uint32_t& r3, uint32_t addr) {
    asm volatile("ldmatrix.sync.aligned.m8n8.x4.shared.b16 {%0,%1,%2,%3}, [%4];"
                 : "=r"(r0), "=r"(r1), "=r"(r2), "=r"(r3) : "r"(addr));
}
__device__ __forceinline__ void mma_h(float& d0, float& d1, float& d2, float& d3,
                                      uint32_t a0, uint32_t a1, uint32_t a2, uint32_t a3,
                                      uint32_t b0, uint32_t b1) {
    asm volatile(
        "mma.sync.aligned.m16n8k16.row.col.f32.f16.f16.f32 "
        "{%0,%1,%2,%3}, {%4,%5,%6,%7}, {%8,%9}, {%0,%1,%2,%3};"
        : "+f"(d0), "+f"(d1), "+f"(d2), "+f"(d3)
        : "r"(a0), "r"(a1), "r"(a2), "r"(a3), "r"(b0), "r"(b1));
}
__device__ __forceinline__ void split_h(float v, __half& h, __half& l) {
    h = __float2half(v);
    l = __float2half(v - __half2float(h));
}
__device__ __forceinline__ float2 h2f2(uint32_t u) {
    return __half22float2(*reinterpret_cast<__half2*>(&u));
}
__device__ __forceinline__ uint32_t pkh2(float a, float b) {
    __half2 t = __floats2half2_rn(a, b);
    return *reinterpret_cast<uint32_t*>(&t);
}

// ===================== small kernels ========================================
// rowptr via edge-boundary scatter (rows sorted ascending)
__global__ void build_rowptr(const int* __restrict__ rows) {
    int e = blockIdx.x * blockDim.x + threadIdx.x;
    if (e >= N_EDGES) return;
    int r  = rows[e];
    int rn = (e + 1 < N_EDGES) ? rows[e + 1] : N_NODES;
    if (e == 0)
        for (int n = 0; n <= r; n++) g_rowptr[n] = 0;
    for (int n = r + 1; n <= rn; n++) g_rowptr[n] = e + 1;
}

// x = fp16(node_emb + type_emb[type])
__global__ void add_emb(const float* __restrict__ node_emb,
                        const float* __restrict__ type_emb,
                        const int* __restrict__ tids) {
    int i = blockIdx.x * blockDim.x + threadIdx.x;          // float4 index
    const int NV = N_NODES * HID / 4;
    if (i >= NV) return;
    int n  = i / (HID / 4);
    int k4 = i % (HID / 4);
    int t  = tids[n];
    float4 a = reinterpret_cast<const float4*>(node_emb)[i];
    float4 b = reinterpret_cast<const float4*>(type_emb)[t * (HID / 4) + k4];
    reinterpret_cast<uint2*>(g_xh)[i] =
        make_uint2(pkh2(a.x + b.x, a.y + b.y), pkh2(a.z + b.z, a.w + b.w));
}

// all 3 weights: W [K,N] fp32 -> Wt_hi/Wt_lo [N,K] fp16 split, one launch
__global__ void prep_w_all(const float* __restrict__ W1, const float* __restrict__ W2,
                           const float* __restrict__ Wp1) {
    int i = blockIdx.x * blockDim.x + threadIdx.x;
    const int S1 = HID * HID;
    const int S2 = S1 + HID * EMB;
    const int S3 = S2 + 3 * EMB * EMB;
    const float* W; __half *hi, *lo; int K, N, j;
    if (i < S1)      { W = W1;  hi = g_w1hi;  lo = g_w1lo;  K = HID;     N = HID; j = i; }
    else if (i < S2) { W = W2;  hi = g_w2hi;  lo = g_w2lo;  K = HID;     N = EMB; j = i - S1; }
    else if (i < S3) { W = Wp1; hi = g_wp1hi; lo = g_wp1lo; K = 3 * EMB; N = EMB; j = i - S2; }
    else return;
    int k = j / N, n = j % N;
    __half h, l;
    split_h(W[j], h, l);
    hi[n * K + k] = h;
    lo[n * K + k] = l;
}

// out[p] = bp2  (pre-init for GEMM3's fused dot epilogue)
__global__ void init_out(float* __restrict__ out, const float* __restrict__ bp2) {
    int i = blockIdx.x * blockDim.x + threadIdx.x;
    if (i < N_PAIRS) out[i] = bp2[0];
}

// ---------------- SpMM: warp-per-node, wide gathers, shuffle indices --------
// Main loop: full 32-edge batches (round-10 structure).
// Remainder: predicated 4-wide unroll -> MLP 4 on the tail, no extra work.
// H=256: lane gathers uint4 (8 halves), unroll 4. H=128: uint2, unroll 8.
// OUT: 0 = fp32 (+bias), 2 = fp16.
template <int H, int OUT>
__global__ void __launch_bounds__(256, 6)
spmm_warp(const __half* __restrict__ x,
          float* __restrict__ yf,
          __half* __restrict__ yh,
          const int* __restrict__ cols,
          const float* __restrict__ vals,
          const float* __restrict__ bias) {
    constexpr int PER = H / 32;     // halves per lane (8 or 4)
    constexpr int UNR = (PER == 8) ? 4 : 8;
    const int lane = threadIdx.x & 31;
    const int n = blockIdx.x * 8 + (threadIdx.x >> 5);
    if (n >= N_NODES) return;

    int e  = g_rowptr[n];
    const int e1 = g_rowptr[n + 1];

    float acc[PER];
#pragma unroll
    for (int k = 0; k < PER; k++) acc[k] = 0.f;

    // full 32-edge batches: coalesced c/v load, shuffle-broadcast
    for (; e + 32 <= e1; e += 32) {
        int   c = __ldg(cols + e + lane);
        float v = __ldg(vals + e + lane);
#pragma unroll UNR
        for (int j = 0; j < 32; j++) {
            int   cj = __shfl_sync(0xffffffffu, c, j);
            float vj = __shfl_sync(0xffffffffu, v, j);
            if (PER == 8) {
                uint4 q = __ldg(reinterpret_cast<const uint4*>(x) +
                                (size_t)cj * (H / 8) + lane);
                float2 f0 = h2f2(q.x), f1 = h2f2(q.y), f2 = h2f2(q.z), f3 = h2f2(q.w);
                acc[0] += vj * f0.x; acc[1] += vj * f0.y;
                acc[2] += vj * f1.x; acc[3] += vj * f1.y;
                acc[4 % PER] += vj * f2.x; acc[5 % PER] += vj * f2.y;
                acc[6 % PER] += vj * f3.x; acc[7 % PER] += vj * f3.y;
            } else {
                uint2 q = __ldg(reinterpret_cast<const uint2*>(x) +
                                (size_t)cj * (H / 4) + lane);
                float2 f0 = h2f2(q.x), f1 = h2f2(q.y);
                acc[0] += vj * f0.x; acc[1] += vj * f0.y;
                acc[2 % PER] += vj * f1.x; acc[3 % PER] += vj * f1.y;
            }
        }
    }
    // remainder: predicated 4-wide groups (loads batched before FFMAs)
    int rem = e1 - e;
    if (rem > 0) {
        int   c = (lane < rem) ? __ldg(cols + e + lane) : 0;
        float v = (lane < rem) ? __ldg(vals + e + lane) : 0.f;
        for (int j0 = 0; j0 < rem; j0 += 4) {
            int   cj[4]; float vj[4];
            uint4 q4[4]; uint2 q2[4];
#pragma unroll
            for (int k = 0; k < 4; k++) {
                int idx = j0 + k;
                cj[k] = __shfl_sync(0xffffffffu, c, idx & 31);
                vj[k] = __shfl_sync(0xffffffffu, v, idx & 31);
                if (PER == 8) {
                    if (idx < rem)
                        q4[k] = __ldg(reinterpret_cast<const uint4*>(x) +
                                      (size_t)cj[k] * (H / 8) + lane);
                } else {
                    if (idx < rem)
                        q2[k] = __ldg(reinterpret_cast<const uint2*>(x) +
                                      (size_t)cj[k] * (H / 4) + lane);
                }
            }
#pragma unroll
            for (int k = 0; k < 4; k++) {
                if (j0 + k >= rem) break;
                if (PER == 8) {
                    float2 f0 = h2f2(q4[k].x), f1 = h2f2(q4[k].y);
                    float2 f2 = h2f2(q4[k].z), f3 = h2f2(q4[k].w);
                    acc[0] += vj[k] * f0.x; acc[1] += vj[k] * f0.y;
                    acc[2] += vj[k] * f1.x; acc[3] += vj[k] * f1.y;
                    acc[4 % PER] += vj[k] * f2.x; acc[5 % PER] += vj[k] * f2.y;
                    acc[6 % PER] += vj[k] * f3.x; acc[7 % PER] += vj[k] * f3.y;
                } else {
                    float2 f0 = h2f2(q2[k].x), f1 = h2f2(q2[k].y);
                    acc[0] += vj[k] * f0.x; acc[1] += vj[k] * f0.y;
                    acc[2 % PER] += vj[k] * f1.x; acc[3 % PER] += vj[k] * f1.y;
                }
            }
        }
    }

    if (OUT == 0) {
#pragma unroll
        for (int k = 0; k < PER; k++)
            if (bias) acc[k] += __ldg(bias + lane * PER + k);
#pragma unroll
        for (int k = 0; k < PER; k += 4) {
            float4 o = make_float4(acc[k], acc[k + 1],
                                   acc[(k + 2) % PER], acc[(k + 3) % PER]);
            *reinterpret_cast<float4*>(yf + (size_t)n * H + lane * PER + k) = o;
        }
    } else {
        uint32_t p[PER / 2];
#pragma unroll
        for (int k = 0; k < PER / 2; k++)
            p[k] = pkh2(acc[2 * k], acc[2 * k + 1]);
        if (PER == 8) {
            uint4 o = make_uint4(p[0], p[1], p[2 % (PER / 2)], p[3 % (PER / 2)]);
            *reinterpret_cast<uint4*>(yh + (size_t)n * H + lane * 8) = o;
        } else {
            uint2 o = make_uint2(p[0], p[1 % (PER / 2)]);
            *reinterpret_cast<uint2*>(yh + (size_t)n * H + lane * 4) = o;
        }
    }
}

// ===================== HMMA GEMM (fp16 A x fp16-split W, 2 products) ========
// C[M, NTOT] = A[M, KTOT] @ W^T  (W fp16 hi/lo, shape [NTOT, KTOT])
// CTA tile 128(M) x 128(N), 8 warps 4x2, warp tile 32x64, kc=32, 2-stage.
// MODE 1: A from Ah_ (fp16); bias+relu fp16 out.
// MODE 3: A from Ah_ (fp16); fp16 out.
// MODE 4: FUSED FEAT — A built on the fly from z fp32 via pairs
//         (seg = chunk/4: 0=z[s], 1=z[d], 2=z[s]*z[d]); bias+relu,
//         dot Wp2v, atomicAdd into Cf (pre-initialized with bp2).
template <int KTOT, int NTOT, int MODE>
__global__ void __launch_bounds__(256, 2)
gemm_mma(const __half* __restrict__ Ah_,
         const __half* __restrict__ Whi,
         const __half* __restrict__ Wlo,
         float* __restrict__ Cf,
         __half* __restrict__ Ch,
         const float* __restrict__ bias,
         const float* __restrict__ Wp2v,
         const float* __restrict__ zf,
         const int* __restrict__ pairs, int M) {
    constexpr int KC = 32;
    constexpr int NS = KTOT / KC;
    constexpr int ST_A  = 0;
    constexpr int ST_WH = 8192;
    constexpr int ST_WL = 16384;
    constexpr int STAGE = 24576;

    extern __shared__ __align__(128) char smem[];
    const uint32_t sb = smem_u32(smem);

    const int tid  = threadIdx.x;
    const int lane = tid & 31;
    const int wm   = (tid >> 5) & 3;
    const int wn   = tid >> 7;
    const int m0   = blockIdx.x * 128;
    const int n0   = blockIdx.y * 128;

    auto load_stage = [&](int ks) {
        const int k0 = ks * KC;
        const uint32_t base = sb + (uint32_t)(ks & 1) * STAGE;
#pragma unroll
        for (int i = 0; i < 2; i++) {
            int id  = tid + i * 256;
            int row = id >> 2;
            int c   = id & 3;
            uint32_t soff = (uint32_t)(row * 64 + ((c ^ ((row >> 1) & 3)) << 4));
            if (MODE == 4) {
                int p = min(m0 + row, M - 1);
                int seg  = ks >> 2;
                int kloc = (ks & 3) * KC + c * 8;
                int s = __ldg(pairs + p);
                int d = __ldg(pairs + N_PAIRS + p);
                uint4 o;
                if (seg == 0) {
                    const float* zp = zf + (size_t)s * EMB + kloc;
                    float4 a0 = *reinterpret_cast<const float4*>(zp);
                    float4 a1 = *reinterpret_cast<const float4*>(zp + 4);
                    o = make_uint4(pkh2(a0.x, a0.y), pkh2(a0.z, a0.w),
                                   pkh2(a1.x, a1.y), pkh2(a1.z, a1.w));
                } else if (seg == 1) {
                    const float* zp = zf + (size_t)d * EMB + kloc;
                    float4 a0 = *reinterpret_cast<const float4*>(zp);
                    float4 a1 = *reinterpret_cast<const float4*>(zp + 4);
                    o = make_uint4(pkh2(a0.x, a0.y), pkh2(a0.z, a0.w),
                                   pkh2(a1.x, a1.y), pkh2(a1.z, a1.w));
                } else {
                    const float* zs = zf + (size_t)s * EMB + kloc;
                    const float* zd = zf + (size_t)d * EMB + kloc;
                    float4 a0 = *reinterpret_cast<const float4*>(zs);
                    float4 a1 = *reinterpret_cast<const float4*>(zs + 4);
                    float4 b0 = *reinterpret_cast<const float4*>(zd);
                    float4 b1 = *reinterpret_cast<const float4*>(zd + 4);
                    o = make_uint4(pkh2(a0.x * b0.x, a0.y * b0.y),
                                   pkh2(a0.z * b0.z, a0.w * b0.w),
                                   pkh2(a1.x * b1.x, a1.y * b1.y),
                                   pkh2(a1.z * b1.z, a1.w * b1.w));
                }
                *reinterpret_cast<uint4*>(smem + ((ks & 1) ? STAGE : 0) + ST_A + soff) = o;
            } else {
                int rowa = min(m0 + row, M - 1);
                cp16(base + ST_A + soff, Ah_ + (size_t)rowa * KTOT + k0 + c * 8);
            }
            size_t goff = (size_t)(n0 + row) * KTOT + k0 + c * 8;
            cp16(base + ST_WH + soff, Whi + goff);
            cp16(base + ST_WL + soff, Wlo + goff);
        }
    };

    float acc[2][8][4];
#pragma unroll
    for (int a = 0; a < 2; a++)
#pragma unroll
        for (int b = 0; b < 8; b++)
#pragma unroll
            for (int c = 0; c < 4; c++) acc[a][b][c] = 0.f;

    const int lrow  = (lane & 7) + ((lane >> 3) & 1) * 8;
    const int khalf = lane >> 4;

    load_stage(0);
    CP_COMMIT();
    if (MODE == 4) __syncthreads();

    for (int ks = 0; ks < NS; ks++) {
        if (ks + 1 < NS) load_stage(ks + 1);
        CP_COMMIT();
        CP_WAIT1();
        __syncthreads();

        const uint32_t base = sb + (uint32_t)(ks & 1) * STAGE;
#pragma unroll
        for (int kk = 0; kk < 2; kk++) {
            const int c = kk * 2 + khalf;
            uint32_t ah[2][4];
#pragma unroll
            for (int mi = 0; mi < 2; mi++) {
                int row = wm * 32 + mi * 16 + lrow;
                uint32_t off = (uint32_t)(row * 64 + ((c ^ ((row >> 1) & 3)) << 4));
                ldsm4(ah[mi][0], ah[mi][1], ah[mi][2], ah[mi][3], base + ST_A + off);
            }
            uint32_t bh[4][4], bl[4][4];
#pragma unroll
            for (int ng = 0; ng < 4; ng++) {
                int row = wn * 64 + ng * 16 + lrow;
                uint32_t off = (uint32_t)(row * 64 + ((c ^ ((row >> 1) & 3)) << 4));
                ldsm4(bh[ng][0], bh[ng][1], bh[ng][2], bh[ng][3], base + ST_WH + off);
                ldsm4(bl[ng][0], bl[ng][1], bl[ng][2], bl[ng][3], base + ST_WL + off);
            }
#pragma unroll
            for (int mi = 0; mi < 2; mi++)
#pragma unroll
                for (int ng = 0; ng < 4; ng++)
#pragma unroll
                    for (int sub = 0; sub < 2; sub++) {
                        int ni = ng * 2 + sub;
                        float* d = acc[mi][ni];
                        mma_h(d[0], d[1], d[2], d[3],
                              ah[mi][0], ah[mi][1], ah[mi][2], ah[mi][3],
                              bh[ng][sub], bh[ng][sub + 2]);
                        mma_h(d[0], d[1], d[2], d[3],
                              ah[mi][0], ah[mi][1], ah[mi][2], ah[mi][3],
                              bl[ng][sub], bl[ng][sub + 2]);
                    }
        }
        __syncthreads();
    }

    // ---- epilogue ----
    if (MODE == 4) {
#pragma unroll
        for (int mi = 0; mi < 2; mi++) {
            float s0 = 0.f, s1 = 0.f;
#pragma unroll
            for (int ni = 0; ni < 8; ni++) {
                int col = n0 + wn * 64 + ni * 8 + 2 * (lane & 3);
                float b0 = __ldg(bias + col),  b1 = __ldg(bias + col + 1);
                float w0 = __ldg(Wp2v + col),  w1 = __ldg(Wp2v + col + 1);
                s0 += fmaxf(acc[mi][ni][0] + b0, 0.f) * w0
                    + fmaxf(acc[mi][ni][1] + b1, 0.f) * w1;
                s1 += fmaxf(acc[mi][ni][2] + b0, 0.f) * w0
                    + fmaxf(acc[mi][ni][3] + b1, 0.f) * w1;
            }
            s0 += __shfl_xor_sync(0xffffffffu, s0, 1);
            s0 += __shfl_xor_sync(0xffffffffu, s0, 2);
            s1 += __shfl_xor_sync(0xffffffffu, s1, 1);
            s1 += __shfl_xor_sync(0xffffffffu, s1, 2);
            if ((lane & 3) == 0) {
                int r0 = m0 + wm * 32 + mi * 16 + (lane >> 2);
                int r1 = r0 + 8;
                if (r0 < M) atomicAdd(Cf + r0, s0);
                if (r1 < M) atomicAdd(Cf + r1, s1);
            }
        }
        return;
    }
#pragma unroll
    for (int mi = 0; mi < 2; mi++) {
        int r0 = m0 + wm * 32 + mi * 16 + (lane >> 2);
        int r1 = r0 + 8;
#pragma unroll
        for (int ni = 0; ni < 8; ni++) {
            int col = n0 + wn * 64 + ni * 8 + 2 * (lane & 3);
            float v0 = acc[mi][ni][0], v1 = acc[mi][ni][1];
            float v2 = acc[mi][ni][2], v3 = acc[mi][ni][3];
            if (MODE == 1) {
                float b0 = __ldg(bias + col), b1 = __ldg(bias + col + 1);
                v0 = fmaxf(v0 + b0, 0.f); v1 = fmaxf(v1 + b1, 0.f);
                v2 = fmaxf(v2 + b0, 0.f); v3 = fmaxf(v3 + b1, 0.f);
            }
            if (r0 < M)
                *reinterpret_cast<uint32_t*>(Ch + (size_t)r0 * NTOT + col) = pkh2(v0, v1);
            if (r1 < M)
                *reinterpret_cast<uint32_t*>(Ch + (size_t)r1 * NTOT + col) = pkh2(v2, v3);
        }
    }
}

// ===========================================================================
extern "C" void kernel_launch(void* const* d_in, const int* in_sizes, int n_in,
                              void* d_out, int out_size) {
    const int*   tids     = (const int*)  d_in[0];
    const int*   rows     = (const int*)  d_in[1];
    const int*   cols     = (const int*)  d_in[2];
    const float* vals     = (const float*)d_in[3];
    const int*   pairs    = (const int*)  d_in[4];
    const float* node_emb = (const float*)d_in[5];
    const float* type_emb = (const float*)d_in[6];
    const float* W1  = (const float*)d_in[7];
    const float* b1  = (const float*)d_in[8];
    const float* W2  = (const float*)d_in[9];
    const float* b2  = (const float*)d_in[10];
    const float* Wp1 = (const float*)d_in[11];
    const float* bp1 = (const float*)d_in[12];
    const float* Wp2 = (const float*)d_in[13];
    const float* bp2 = (const float*)d_in[14];
    float* out = (float*)d_out;

    void *pxh, *paxh, *phh, *phwh, *pz;
    void *w1h, *w1l, *w2h, *w2l, *wp1h, *wp1l;
    cudaGetSymbolAddress(&pxh,  g_xh);
    cudaGetSymbolAddress(&paxh, g_axh);
    cudaGetSymbolAddress(&phh,  g_hh);
    cudaGetSymbolAddress(&phwh, g_hwh);
    cudaGetSymbolAddress(&pz,   g_z);
    cudaGetSymbolAddress(&w1h,  g_w1hi);  cudaGetSymbolAddress(&w1l, g_w1lo);
    cudaGetSymbolAddress(&w2h,  g_w2hi);  cudaGetSymbolAddress(&w2l, g_w2lo);
    cudaGetSymbolAddress(&wp1h, g_wp1hi); cudaGetSymbolAddress(&wp1l, g_wp1lo);

    constexpr int SMEM = 2 * 24576;   // 48 KB
    cudaFuncSetAttribute(gemm_mma<256, 256, 1>,
                         cudaFuncAttributeMaxDynamicSharedMemorySize, SMEM);
    cudaFuncSetAttribute(gemm_mma<256, 128, 3>,
                         cudaFuncAttributeMaxDynamicSharedMemorySize, SMEM);
    cudaFuncSetAttribute(gemm_mma<384, 128, 4>,
                         cudaFuncAttributeMaxDynamicSharedMemorySize, SMEM);

    // 0. weight prep (one launch, transpose + fp16 split)
    {
        int tot = HID * HID + HID * EMB + 3 * EMB * EMB;
        prep_w_all<<<(tot + 255) / 256, 256>>>(W1, W2, Wp1);
    }
    // 1. row_ptr (edge-boundary scatter)
    build_rowptr<<<(N_EDGES + 255) / 256, 256>>>(rows);
    // 2. x = fp16(node_emb + type_emb[type])
    add_emb<<<(N_NODES * HID / 4 + 255) / 256, 256>>>(node_emb, type_emb, tids);
    // 3. ax = spmm(x) -> fp16   [warp-per-node, MLP remainder]
    spmm_warp<HID, 2><<<(N_NODES + 7) / 8, 256>>>(
        (const __half*)pxh, nullptr, (__half*)paxh, cols, vals, nullptr);
    // 4. h = relu(ax @ W1 + b1) -> fp16   [HMMA 128x128]
    {
        dim3 grid((N_NODES + 127) / 128, HID / 128);
        gemm_mma<256, 256, 1><<<grid, 256, SMEM>>>(
            (const __half*)paxh, (const __half*)w1h, (const __half*)w1l,
            nullptr, (__half*)phh, b1, nullptr, nullptr, nullptr, N_NODES);
    }
    // 5. hw = h @ W2 -> fp16   [HMMA 128x128]
    {
        dim3 grid((N_NODES + 127) / 128, EMB / 128);
        gemm_mma<256, 128, 3><<<grid, 256, SMEM>>>(
            (const __half*)phh, (const __half*)w2h, (const __half*)w2l,
            nullptr, (__half*)phwh, nullptr, nullptr, nullptr, nullptr, N_NODES);
    }
    // 6. z = spmm(hw) + b2  (fp32)   [warp-per-node, MLP remainder]
    spmm_warp<EMB, 0><<<(N_NODES + 7) / 8, 256>>>(
        (const __half*)phwh, (float*)pz, nullptr, cols, vals, b2);
    // 7+8. out = relu(feat @ Wp1 + bp1) @ Wp2 + bp2  [fused feat + HMMA + dot]
    init_out<<<(N_PAIRS + 255) / 256, 256>>>(out, bp2);
    {
        dim3 grid((N_PAIRS + 127) / 128, EMB / 128);
        gemm_mma<384, 128, 4><<<grid, 256, SMEM>>>(
            nullptr, (const __half*)wp1h, (const __half*)wp1l,
            out, nullptr, bp1, Wp2, (const float*)pz, pairs, N_PAIRS);
    }
}

// round 13
// speedup vs baseline: 1.1398x; 1.1375x over previous
#include <cuda_runtime.h>
#include <cuda_fp16.h>
#include <cstdint>

#define N_NODES 100000
#define N_EDGES 3200000
#define HID 256
#define EMB 128
#define N_PAIRS 100000

// ===================== scratch (device globals) =============================
__device__ __half g_xh [N_NODES * HID];         // spmm1 input (fp16)
__device__ __half g_axh[N_NODES * HID];         // spmm1 out = GEMM1 A (fp16)
__device__ __half g_hh [N_NODES * HID];         // GEMM1 out = GEMM2 A (fp16)
__device__ __half g_hwh[N_NODES * EMB];         // GEMM2 out (fp16, feeds spmm2)
__device__ float  g_z  [N_NODES * EMB];         // spmm2 out (fp32)
__device__ int    g_rowptr[N_NODES + 1];
// transposed + fp16-split weights: [N][K]
__device__ __half g_w1hi[HID * HID],      g_w1lo[HID * HID];
__device__ __half g_w2hi[EMB * HID],      g_w2lo[EMB * HID];
__device__ __half g_wp1hi[EMB * 3 * EMB], g_wp1lo[EMB * 3 * EMB];

// ===================== helpers ==============================================
__device__ __forceinline__ uint32_t smem_u32(const void* p) {
    uint32_t a;
    asm("{ .reg .u64 t; cvta.to.shared.u64 t, %1; cvt.u32.u64 %0, t; }"
        : "=r"(a) : "l"(p));
    return a;
}
__device__ __forceinline__ void cp16(uint32_t dst, const void* src) {
    asm volatile("cp.async.cg.shared.global [%0], [%1], 16;" :: "r"(dst), "l"(src));
}
#define CP_COMMIT() asm volatile("cp.async.commit_group;" ::: "memory")
#define CP_WAIT2()  asm volatile("cp.async.wait_group 2;" ::: "memory")

__device__ __forceinline__ void ldsm4(uint32_t& r0, uint32_t& r1,
                                      uint32_t& r2, uint32_t& r3, uint32_t addr) {
    asm volatile("ldmatrix.sync.aligned.m8n8.x4.shared.b16 {%0,%1,%2,%3}, [%4];"
                 : "=r"(r0), "=r"(r1), "=r"(r2), "=r"(r3) : "r"(addr));
}
__device__ __forceinline__ void mma_h(float& d0, float& d1, float& d2, float& d3,
                                      uint32_t a0, uint32_t a1, uint32_t a2, uint32_t a3,
                                      uint32_t b0, uint32_t b1) {
    asm volatile(
        "mma.sync.aligned.m16n8k16.row.col.f32.f16.f16.f32 "
        "{%0,%1,%2,%3}, {%4,%5,%6,%7}, {%8,%9}, {%0,%1,%2,%3};"
        : "+f"(d0), "+f"(d1), "+f"(d2), "+f"(d3)
        : "r"(a0), "r"(a1), "r"(a2), "r"(a3), "r"(b0), "r"(b1));
}
__device__ __forceinline__ void split_h(float v, __half& h, __half& l) {
    h = __float2half(v);
    l = __float2half(v - __half2float(h));
}
__device__ __forceinline__ float2 h2f2(uint32_t u) {
    return __half22float2(*reinterpret_cast<__half2*>(&u));
}
__device__ __forceinline__ uint32_t pkh2(float a, float b) {
    __half2 t = __floats2half2_rn(a, b);
    return *reinterpret_cast<uint32_t*>(&t);
}

// ===================== small kernels ========================================
// rowptr via edge-boundary scatter (rows sorted ascending)
__global__ void build_rowptr(const int* __restrict__ rows) {
    int e = blockIdx.x * blockDim.x + threadIdx.x;
    if (e >= N_EDGES) return;
    int r  = rows[e];
    int rn = (e + 1 < N_EDGES) ? rows[e + 1] : N_NODES;
    if (e == 0)
        for (int n = 0; n <= r; n++) g_rowptr[n] = 0;
    for (int n = r + 1; n <= rn; n++) g_rowptr[n] = e + 1;
}

// x = fp16(node_emb + type_emb[type])
__global__ void add_emb(const float* __restrict__ node_emb,
                        const float* __restrict__ type_emb,
                        const int* __restrict__ tids) {
    int i = blockIdx.x * blockDim.x + threadIdx.x;          // float4 index
    const int NV = N_NODES * HID / 4;
    if (i >= NV) return;
    int n  = i / (HID / 4);
    int k4 = i % (HID / 4);
    int t  = tids[n];
    float4 a = reinterpret_cast<const float4*>(node_emb)[i];
    float4 b = reinterpret_cast<const float4*>(type_emb)[t * (HID / 4) + k4];
    reinterpret_cast<uint2*>(g_xh)[i] =
        make_uint2(pkh2(a.x + b.x, a.y + b.y), pkh2(a.z + b.z, a.w + b.w));
}

// all 3 weights: W [K,N] fp32 -> Wt_hi/Wt_lo [N,K] fp16 split, one launch
__global__ void prep_w_all(const float* __restrict__ W1, const float* __restrict__ W2,
                           const float* __restrict__ Wp1) {
    int i = blockIdx.x * blockDim.x + threadIdx.x;
    const int S1 = HID * HID;
    const int S2 = S1 + HID * EMB;
    const int S3 = S2 + 3 * EMB * EMB;
    const float* W; __half *hi, *lo; int K, N, j;
    if (i < S1)      { W = W1;  hi = g_w1hi;  lo = g_w1lo;  K = HID;     N = HID; j = i; }
    else if (i < S2) { W = W2;  hi = g_w2hi;  lo = g_w2lo;  K = HID;     N = EMB; j = i - S1; }
    else if (i < S3) { W = Wp1; hi = g_wp1hi; lo = g_wp1lo; K = 3 * EMB; N = EMB; j = i - S2; }
    else return;
    int k = j / N, n = j % N;
    __half h, l;
    split_h(W[j], h, l);
    hi[n * K + k] = h;
    lo[n * K + k] = l;
}

// out[p] = bp2  (pre-init for GEMM3's fused dot epilogue)
__global__ void init_out(float* __restrict__ out, const float* __restrict__ bp2) {
    int i = blockIdx.x * blockDim.x + threadIdx.x;
    if (i < N_PAIRS) out[i] = bp2[0];
}

// ---------------- SpMM: warp-per-node (round-10 structure, FROZEN) ----------
// H=256: lane gathers uint4 (8 halves), unroll 4. H=128: uint2, unroll 8.
// OUT: 0 = fp32 (+bias), 2 = fp16.
template <int H, int OUT>
__global__ void __launch_bounds__(256, 6)
spmm_warp(const __half* __restrict__ x,
          float* __restrict__ yf,
          __half* __restrict__ yh,
          const int* __restrict__ cols,
          const float* __restrict__ vals,
          const float* __restrict__ bias) {
    constexpr int PER = H / 32;     // halves per lane (8 or 4)
    constexpr int UNR = (PER == 8) ? 4 : 8;
    const int lane = threadIdx.x & 31;
    const int n = blockIdx.x * 8 + (threadIdx.x >> 5);
    if (n >= N_NODES) return;

    int e  = g_rowptr[n];
    const int e1 = g_rowptr[n + 1];

    float acc[PER];
#pragma unroll
    for (int k = 0; k < PER; k++) acc[k] = 0.f;

    // full 32-edge batches: coalesced c/v load, shuffle-broadcast
    for (; e + 32 <= e1; e += 32) {
        int   c = __ldg(cols + e + lane);
        float v = __ldg(vals + e + lane);
#pragma unroll UNR
        for (int j = 0; j < 32; j++) {
            int   cj = __shfl_sync(0xffffffffu, c, j);
            float vj = __shfl_sync(0xffffffffu, v, j);
            if (PER == 8) {
                uint4 q = __ldg(reinterpret_cast<const uint4*>(x) +
                                (size_t)cj * (H / 8) + lane);
                float2 f0 = h2f2(q.x), f1 = h2f2(q.y), f2 = h2f2(q.z), f3 = h2f2(q.w);
                acc[0] += vj * f0.x; acc[1] += vj * f0.y;
                acc[2] += vj * f1.x; acc[3] += vj * f1.y;
                acc[4 % PER] += vj * f2.x; acc[5 % PER] += vj * f2.y;
                acc[6 % PER] += vj * f3.x; acc[7 % PER] += vj * f3.y;
            } else {
                uint2 q = __ldg(reinterpret_cast<const uint2*>(x) +
                                (size_t)cj * (H / 4) + lane);
                float2 f0 = h2f2(q.x), f1 = h2f2(q.y);
                acc[0] += vj * f0.x; acc[1] += vj * f0.y;
                acc[2 % PER] += vj * f1.x; acc[3 % PER] += vj * f1.y;
            }
        }
    }
    // remainder
    int rem = e1 - e;
    if (rem > 0) {
        int   c = (lane < rem) ? __ldg(cols + e + lane) : 0;
        float v = (lane < rem) ? __ldg(vals + e + lane) : 0.f;
        for (int j = 0; j < rem; j++) {
            int   cj = __shfl_sync(0xffffffffu, c, j);
            float vj = __shfl_sync(0xffffffffu, v, j);
            if (PER == 8) {
                uint4 q = __ldg(reinterpret_cast<const uint4*>(x) +
                                (size_t)cj * (H / 8) + lane);
                float2 f0 = h2f2(q.x), f1 = h2f2(q.y), f2 = h2f2(q.z), f3 = h2f2(q.w);
                acc[0] += vj * f0.x; acc[1] += vj * f0.y;
                acc[2] += vj * f1.x; acc[3] += vj * f1.y;
                acc[4 % PER] += vj * f2.x; acc[5 % PER] += vj * f2.y;
                acc[6 % PER] += vj * f3.x; acc[7 % PER] += vj * f3.y;
            } else {
                uint2 q = __ldg(reinterpret_cast<const uint2*>(x) +
                                (size_t)cj * (H / 4) + lane);
                float2 f0 = h2f2(q.x), f1 = h2f2(q.y);
                acc[0] += vj * f0.x; acc[1] += vj * f0.y;
                acc[2 % PER] += vj * f1.x; acc[3 % PER] += vj * f1.y;
            }
        }
    }

    if (OUT == 0) {
#pragma unroll
        for (int k = 0; k < PER; k++)
            if (bias) acc[k] += __ldg(bias + lane * PER + k);
#pragma unroll
        for (int k = 0; k < PER; k += 4) {
            float4 o = make_float4(acc[k], acc[k + 1],
                                   acc[(k + 2) % PER], acc[(k + 3) % PER]);
            *reinterpret_cast<float4*>(yf + (size_t)n * H + lane * PER + k) = o;
        }
    } else {
        uint32_t p[PER / 2];
#pragma unroll
        for (int k = 0; k < PER / 2; k++)
            p[k] = pkh2(acc[2 * k], acc[2 * k + 1]);
        if (PER == 8) {
            uint4 o = make_uint4(p[0], p[1], p[2 % (PER / 2)], p[3 % (PER / 2)]);
            *reinterpret_cast<uint4*>(yh + (size_t)n * H + lane * 8) = o;
        } else {
            uint2 o = make_uint2(p[0], p[1 % (PER / 2)]);
            *reinterpret_cast<uint2*>(yh + (size_t)n * H + lane * 4) = o;
        }
    }
}

// ===================== HMMA GEMM (fp16 A x fp16-split W, 2 products) ========
// C[M, NTOT] = A[M, KTOT] @ W^T  (W fp16 hi/lo, shape [NTOT, KTOT])
// CTA tile 128(M) x 128(N), 8 warps 4x2, warp tile 32x64, kc=32,
// *** 3-stage cp.async pipeline *** (wait_group 2).
// MODE 1: A from Ah_ (fp16); bias+relu fp16 out.
// MODE 3: A from Ah_ (fp16); fp16 out.
// MODE 4: FUSED FEAT — A built on the fly from z fp32 via pairs
//         (seg = chunk/4: 0=z[s], 1=z[d], 2=z[s]*z[d]); bias+relu,
//         dot Wp2v, atomicAdd into Cf (pre-initialized with bp2).
template <int KTOT, int NTOT, int MODE>
__global__ void __launch_bounds__(256, 2)
gemm_mma(const __half* __restrict__ Ah_,
         const __half* __restrict__ Whi,
         const __half* __restrict__ Wlo,
         float* __restrict__ Cf,
         __half* __restrict__ Ch,
         const float* __restrict__ bias,
         const float* __restrict__ Wp2v,
         const float* __restrict__ zf,
         const int* __restrict__ pairs, int M) {
    constexpr int KC = 32;
    constexpr int NS = KTOT / KC;
    constexpr int ST_A  = 0;
    constexpr int ST_WH = 8192;
    constexpr int ST_WL = 16384;
    constexpr int STAGE = 24576;

    extern __shared__ __align__(128) char smem[];
    const uint32_t sb = smem_u32(smem);

    const int tid  = threadIdx.x;
    const int lane = tid & 31;
    const int wm   = (tid >> 5) & 3;
    const int wn   = tid >> 7;
    const int m0   = blockIdx.x * 128;
    const int n0   = blockIdx.y * 128;

    auto load_stage = [&](int ks) {
        const int k0 = ks * KC;
        const int slot = ks % 3;
        const uint32_t base = sb + (uint32_t)slot * STAGE;
#pragma unroll
        for (int i = 0; i < 2; i++) {
            int id  = tid + i * 256;
            int row = id >> 2;
            int c   = id & 3;
            uint32_t soff = (uint32_t)(row * 64 + ((c ^ ((row >> 1) & 3)) << 4));
            if (MODE == 4) {
                int p = min(m0 + row, M - 1);
                int seg  = ks >> 2;
                int kloc = (ks & 3) * KC + c * 8;
                int s = __ldg(pairs + p);
                int d = __ldg(pairs + N_PAIRS + p);
                uint4 o;
                if (seg == 0) {
                    const float* zp = zf + (size_t)s * EMB + kloc;
                    float4 a0 = *reinterpret_cast<const float4*>(zp);
                    float4 a1 = *reinterpret_cast<const float4*>(zp + 4);
                    o = make_uint4(pkh2(a0.x, a0.y), pkh2(a0.z, a0.w),
                                   pkh2(a1.x, a1.y), pkh2(a1.z, a1.w));
                } else if (seg == 1) {
                    const float* zp = zf + (size_t)d * EMB + kloc;
                    float4 a0 = *reinterpret_cast<const float4*>(zp);
                    float4 a1 = *reinterpret_cast<const float4*>(zp + 4);
                    o = make_uint4(pkh2(a0.x, a0.y), pkh2(a0.z, a0.w),
                                   pkh2(a1.x, a1.y), pkh2(a1.z, a1.w));
                } else {
                    const float* zs = zf + (size_t)s * EMB + kloc;
                    const float* zd = zf + (size_t)d * EMB + kloc;
                    float4 a0 = *reinterpret_cast<const float4*>(zs);
                    float4 a1 = *reinterpret_cast<const float4*>(zs + 4);
                    float4 b0 = *reinterpret_cast<const float4*>(zd);
                    float4 b1 = *reinterpret_cast<const float4*>(zd + 4);
                    o = make_uint4(pkh2(a0.x * b0.x, a0.y * b0.y),
                                   pkh2(a0.z * b0.z, a0.w * b0.w),
                                   pkh2(a1.x * b1.x, a1.y * b1.y),
                                   pkh2(a1.z * b1.z, a1.w * b1.w));
                }
                *reinterpret_cast<uint4*>(smem + slot * STAGE + ST_A + soff) = o;
            } else {
                int rowa = min(m0 + row, M - 1);
                cp16(base + ST_A + soff, Ah_ + (size_t)rowa * KTOT + k0 + c * 8);
            }
            size_t goff = (size_t)(n0 + row) * KTOT + k0 + c * 8;
            cp16(base + ST_WH + soff, Whi + goff);
            cp16(base + ST_WL + soff, Wlo + goff);
        }
    };

    float acc[2][8][4];
#pragma unroll
    for (int a = 0; a < 2; a++)
#pragma unroll
        for (int b = 0; b < 8; b++)
#pragma unroll
            for (int c = 0; c < 4; c++) acc[a][b][c] = 0.f;

    const int lrow  = (lane & 7) + ((lane >> 3) & 1) * 8;
    const int khalf = lane >> 4;

    // prologue: stages 0 and 1 in flight
    load_stage(0);
    CP_COMMIT();
    if (NS > 1) load_stage(1);
    CP_COMMIT();

    for (int ks = 0; ks < NS; ks++) {
        if (ks + 2 < NS) load_stage(ks + 2);
        CP_COMMIT();
        CP_WAIT2();            // oldest stage (ks) complete
        __syncthreads();

        const uint32_t base = sb + (uint32_t)(ks % 3) * STAGE;
#pragma unroll
        for (int kk = 0; kk < 2; kk++) {
            const int c = kk * 2 + khalf;
            uint32_t ah[2][4];
#pragma unroll
            for (int mi = 0; mi < 2; mi++) {
                int row = wm * 32 + mi * 16 + lrow;
                uint32_t off = (uint32_t)(row * 64 + ((c ^ ((row >> 1) & 3)) << 4));
                ldsm4(ah[mi][0], ah[mi][1], ah[mi][2], ah[mi][3], base + ST_A + off);
            }
            uint32_t bh[4][4], bl[4][4];
#pragma unroll
            for (int ng = 0; ng < 4; ng++) {
                int row = wn * 64 + ng * 16 + lrow;
                uint32_t off = (uint32_t)(row * 64 + ((c ^ ((row >> 1) & 3)) << 4));
                ldsm4(bh[ng][0], bh[ng][1], bh[ng][2], bh[ng][3], base + ST_WH + off);
                ldsm4(bl[ng][0], bl[ng][1], bl[ng][2], bl[ng][3], base + ST_WL + off);
            }
#pragma unroll
            for (int mi = 0; mi < 2; mi++)
#pragma unroll
                for (int ng = 0; ng < 4; ng++)
#pragma unroll
                    for (int sub = 0; sub < 2; sub++) {
                        int ni = ng * 2 + sub;
                        float* d = acc[mi][ni];
                        mma_h(d[0], d[1], d[2], d[3],
                              ah[mi][0], ah[mi][1], ah[mi][2], ah[mi][3],
                              bh[ng][sub], bh[ng][sub + 2]);
                        mma_h(d[0], d[1], d[2], d[3],
                              ah[mi][0], ah[mi][1], ah[mi][2], ah[mi][3],
                              bl[ng][sub], bl[ng][sub + 2]);
                    }
        }
        __syncthreads();
    }

    // ---- epilogue ----
    if (MODE == 4) {
#pragma unroll
        for (int mi = 0; mi < 2; mi++) {
            float s0 = 0.f, s1 = 0.f;
#pragma unroll
            for (int ni = 0; ni < 8; ni++) {
                int col = n0 + wn * 64 + ni * 8 + 2 * (lane & 3);
                float b0 = __ldg(bias + col),  b1 = __ldg(bias + col + 1);
                float w0 = __ldg(Wp2v + col),  w1 = __ldg(Wp2v + col + 1);
                s0 += fmaxf(acc[mi][ni][0] + b0, 0.f) * w0
                    + fmaxf(acc[mi][ni][1] + b1, 0.f) * w1;
                s1 += fmaxf(acc[mi][ni][2] + b0, 0.f) * w0
                    + fmaxf(acc[mi][ni][3] + b1, 0.f) * w1;
            }
            s0 += __shfl_xor_sync(0xffffffffu, s0, 1);
            s0 += __shfl_xor_sync(0xffffffffu, s0, 2);
            s1 += __shfl_xor_sync(0xffffffffu, s1, 1);
            s1 += __shfl_xor_sync(0xffffffffu, s1, 2);
            if ((lane & 3) == 0) {
                int r0 = m0 + wm * 32 + mi * 16 + (lane >> 2);
                int r1 = r0 + 8;
                if (r0 < M) atomicAdd(Cf + r0, s0);
                if (r1 < M) atomicAdd(Cf + r1, s1);
            }
        }
        return;
    }
#pragma unroll
    for (int mi = 0; mi < 2; mi++) {
        int r0 = m0 + wm * 32 + mi * 16 + (lane >> 2);
        int r1 = r0 + 8;
#pragma unroll
        for (int ni = 0; ni < 8; ni++) {
            int col = n0 + wn * 64 + ni * 8 + 2 * (lane & 3);
            float v0 = acc[mi][ni][0], v1 = acc[mi][ni][1];
            float v2 = acc[mi][ni][2], v3 = acc[mi][ni][3];
            if (MODE == 1) {
                float b0 = __ldg(bias + col), b1 = __ldg(bias + col + 1);
                v0 = fmaxf(v0 + b0, 0.f); v1 = fmaxf(v1 + b1, 0.f);
                v2 = fmaxf(v2 + b0, 0.f); v3 = fmaxf(v3 + b1, 0.f);
            }
            if (r0 < M)
                *reinterpret_cast<uint32_t*>(Ch + (size_t)r0 * NTOT + col) = pkh2(v0, v1);
            if (r1 < M)
                *reinterpret_cast<uint32_t*>(Ch + (size_t)r1 * NTOT + col) = pkh2(v2, v3);
        }
    }
}

// ===========================================================================
extern "C" void kernel_launch(void* const* d_in, const int* in_sizes, int n_in,
                              void* d_out, int out_size) {
    const int*   tids     = (const int*)  d_in[0];
    const int*   rows     = (const int*)  d_in[1];
    const int*   cols     = (const int*)  d_in[2];
    const float* vals     = (const float*)d_in[3];
    const int*   pairs    = (const int*)  d_in[4];
    const float* node_emb = (const float*)d_in[5];
    const float* type_emb = (const float*)d_in[6];
    const float* W1  = (const float*)d_in[7];
    const float* b1  = (const float*)d_in[8];
    const float* W2  = (const float*)d_in[9];
    const float* b2  = (const float*)d_in[10];
    const float* Wp1 = (const float*)d_in[11];
    const float* bp1 = (const float*)d_in[12];
    const float* Wp2 = (const float*)d_in[13];
    const float* bp2 = (const float*)d_in[14];
    float* out = (float*)d_out;

    void *pxh, *paxh, *phh, *phwh, *pz;
    void *w1h, *w1l, *w2h, *w2l, *wp1h, *wp1l;
    cudaGetSymbolAddress(&pxh,  g_xh);
    cudaGetSymbolAddress(&paxh, g_axh);
    cudaGetSymbolAddress(&phh,  g_hh);
    cudaGetSymbolAddress(&phwh, g_hwh);
    cudaGetSymbolAddress(&pz,   g_z);
    cudaGetSymbolAddress(&w1h,  g_w1hi);  cudaGetSymbolAddress(&w1l, g_w1lo);
    cudaGetSymbolAddress(&w2h,  g_w2hi);  cudaGetSymbolAddress(&w2l, g_w2lo);
    cudaGetSymbolAddress(&wp1h, g_wp1hi); cudaGetSymbolAddress(&wp1l, g_wp1lo);

    constexpr int SMEM = 3 * 24576;   // 72 KB (3-stage)
    cudaFuncSetAttribute(gemm_mma<256, 256, 1>,
                         cudaFuncAttributeMaxDynamicSharedMemorySize, SMEM);
    cudaFuncSetAttribute(gemm_mma<256, 128, 3>,
                         cudaFuncAttributeMaxDynamicSharedMemorySize, SMEM);
    cudaFuncSetAttribute(gemm_mma<384, 128, 4>,
                         cudaFuncAttributeMaxDynamicSharedMemorySize, SMEM);

    // 0. weight prep (one launch, transpose + fp16 split)
    {
        int tot = HID * HID + HID * EMB + 3 * EMB * EMB;
        prep_w_all<<<(tot + 255) / 256, 256>>>(W1, W2, Wp1);
    }
    // 1. row_ptr (edge-boundary scatter)
    build_rowptr<<<(N_EDGES + 255) / 256, 256>>>(rows);
    // 2. x = fp16(node_emb + type_emb[type])
    add_emb<<<(N_NODES * HID / 4 + 255) / 256, 256>>>(node_emb, type_emb, tids);
    // 3. ax = spmm(x) -> fp16   [round-10 spmm, frozen]
    spmm_warp<HID, 2><<<(N_NODES + 7) / 8, 256>>>(
        (const __half*)pxh, nullptr, (__half*)paxh, cols, vals, nullptr);
    // 4. h = relu(ax @ W1 + b1) -> fp16   [HMMA 128x128, 3-stage]
    {
        dim3 grid((N_NODES + 127) / 128, HID / 128);
        gemm_mma<256, 256, 1><<<grid, 256, SMEM>>>(
            (const __half*)paxh, (const __half*)w1h, (const __half*)w1l,
            nullptr, (__half*)phh, b1, nullptr, nullptr, nullptr, N_NODES);
    }
    // 5. hw = h @ W2 -> fp16   [HMMA 128x128, 3-stage]
    {
        dim3 grid((N_NODES + 127) / 128, EMB / 128);
        gemm_mma<256, 128, 3><<<grid, 256, SMEM>>>(
            (const __half*)phh, (const __half*)w2h, (const __half*)w2l,
            nullptr, (__half*)phwh, nullptr, nullptr, nullptr, nullptr, N_NODES);
    }
    // 6. z = spmm(hw) + b2  (fp32)   [round-10 spmm, frozen]
    spmm_warp<EMB, 0><<<(N_NODES + 7) / 8, 256>>>(
        (const __half*)phwh, (float*)pz, nullptr, cols, vals, b2);
    // 7+8. out = relu(feat @ Wp1 + bp1) @ Wp2 + bp2  [fused feat + HMMA + dot]
    init_out<<<(N_PAIRS + 255) / 256, 256>>>(out, bp2);
    {
        dim3 grid((N_PAIRS + 127) / 128, EMB / 128);
        gemm_mma<384, 128, 4><<<grid, 256, SMEM>>>(
            nullptr, (const __half*)wp1h, (const __half*)wp1l,
            out, nullptr, bp1, Wp2, (const float*)pz, pairs, N_PAIRS);
    }
}

// round 14
// speedup vs baseline: 1.1526x; 1.0112x over previous
#include <cuda_runtime.h>
#include <cuda_fp16.h>
#include <cstdint>

#define N_NODES 100000
#define N_EDGES 3200000
#define HID 256
#define EMB 128
#define N_PAIRS 100000

// ===================== scratch (device globals) =============================
__device__ __half g_xh [N_NODES * HID];         // spmm1 input (fp16)
__device__ __half g_axh[N_NODES * HID];         // spmm1 out = GEMM1 A (fp16)
__device__ __half g_hh [N_NODES * HID];         // GEMM1 out = GEMM2 A (fp16)
__device__ __half g_hwh[N_NODES * EMB];         // GEMM2 out (fp16, feeds spmm2)
__device__ float  g_z  [N_NODES * EMB];         // spmm2 out (fp32)
__device__ int    g_rowptr[N_NODES + 1];
// transposed + fp16-split weights: [N][K]
__device__ __half g_w1hi[HID * HID],      g_w1lo[HID * HID];
__device__ __half g_w2hi[EMB * HID],      g_w2lo[EMB * HID];
__device__ __half g_wp1hi[EMB * 3 * EMB], g_wp1lo[EMB * 3 * EMB];

// ===================== helpers ==============================================
__device__ __forceinline__ uint32_t smem_u32(const void* p) {
    uint32_t a;
    asm("{ .reg .u64 t; cvta.to.shared.u64 t, %1; cvt.u32.u64 %0, t; }"
        : "=r"(a) : "l"(p));
    return a;
}
__device__ __forceinline__ void cp16(uint32_t dst, const void* src) {
    asm volatile("cp.async.cg.shared.global [%0], [%1], 16;" :: "r"(dst), "l"(src));
}
#define CP_COMMIT() asm volatile("cp.async.commit_group;" ::: "memory")
#define CP_WAIT1()  asm volatile("cp.async.wait_group 1;" ::: "memory")

__device__ __forceinline__ void ldsm4(uint32_t& r0, uint32_t& r1,
                                      uint32_t& r2, uint32_t& r3, uint32_t addr) {
    asm volatile("ldmatrix.sync.aligned.m8n8.x4.shared.b16 {%0,%1,%2,%3}, [%4];"
                 : "=r"(r0), "=r"(r1), "=r"(r2), "=r"(r3) : "r"(addr));
}
__device__ __forceinline__ void mma_h(float& d0, float& d1, float& d2, float& d3,
                                      uint32_t a0, uint32_t a1, uint32_t a2, uint32_t a3,
                                      uint32_t b0, uint32_t b1) {
    asm volatile(
        "mma.sync.aligned.m16n8k16.row.col.f32.f16.f16.f32 "
        "{%0,%1,%2,%3}, {%4,%5,%6,%7}, {%8,%9}, {%0,%1,%2,%3};"
        : "+f"(d0), "+f"(d1), "+f"(d2), "+f"(d3)
        : "r"(a0), "r"(a1), "r"(a2), "r"(a3), "r"(b0), "r"(b1));
}
__device__ __forceinline__ void split_h(float v, __half& h, __half& l) {
    h = __float2half(v);
    l = __float2half(v - __half2float(h));
}
__device__ __forceinline__ float2 h2f2(uint32_t u) {
    return __half22float2(*reinterpret_cast<__half2*>(&u));
}
__device__ __forceinline__ uint32_t pkh2(float a, float b) {
    __half2 t = __floats2half2_rn(a, b);
    return *reinterpret_cast<uint32_t*>(&t);
}

// ===================== small kernels ========================================
// rowptr via edge-boundary scatter (rows sorted ascending)
__global__ void build_rowptr(const int* __restrict__ rows) {
    int e = blockIdx.x * blockDim.x + threadIdx.x;
    if (e >= N_EDGES) return;
    int r  = rows[e];
    int rn = (e + 1 < N_EDGES) ? rows[e + 1] : N_NODES;
    if (e == 0)
        for (int n = 0; n <= r; n++) g_rowptr[n] = 0;
    for (int n = r + 1; n <= rn; n++) g_rowptr[n] = e + 1;
}

// x = fp16(node_emb + type_emb[type])
__global__ void add_emb(const float* __restrict__ node_emb,
                        const float* __restrict__ type_emb,
                        const int* __restrict__ tids) {
    int i = blockIdx.x * blockDim.x + threadIdx.x;          // float4 index
    const int NV = N_NODES * HID / 4;
    if (i >= NV) return;
    int n  = i / (HID / 4);
    int k4 = i % (HID / 4);
    int t  = tids[n];
    float4 a = reinterpret_cast<const float4*>(node_emb)[i];
    float4 b = reinterpret_cast<const float4*>(type_emb)[t * (HID / 4) + k4];
    reinterpret_cast<uint2*>(g_xh)[i] =
        make_uint2(pkh2(a.x + b.x, a.y + b.y), pkh2(a.z + b.z, a.w + b.w));
}

// all 3 weights: W [K,N] fp32 -> Wt_hi/Wt_lo [N,K] fp16 split, one launch
__global__ void prep_w_all(const float* __restrict__ W1, const float* __restrict__ W2,
                           const float* __restrict__ Wp1) {
    int i = blockIdx.x * blockDim.x + threadIdx.x;
    const int S1 = HID * HID;
    const int S2 = S1 + HID * EMB;
    const int S3 = S2 + 3 * EMB * EMB;
    const float* W; __half *hi, *lo; int K, N, j;
    if (i < S1)      { W = W1;  hi = g_w1hi;  lo = g_w1lo;  K = HID;     N = HID; j = i; }
    else if (i < S2) { W = W2;  hi = g_w2hi;  lo = g_w2lo;  K = HID;     N = EMB; j = i - S1; }
    else if (i < S3) { W = Wp1; hi = g_wp1hi; lo = g_wp1lo; K = 3 * EMB; N = EMB; j = i - S2; }
    else return;
    int k = j / N, n = j % N;
    __half h, l;
    split_h(W[j], h, l);
    hi[n * K + k] = h;
    lo[n * K + k] = l;
}

// out[p] = bp2  (pre-init for GEMM3's fused dot epilogue)
__global__ void init_out(float* __restrict__ out, const float* __restrict__ bp2) {
    int i = blockIdx.x * blockDim.x + threadIdx.x;
    if (i < N_PAIRS) out[i] = bp2[0];
}

// ---------------- SpMM: warp-per-node (round-10 structure, FROZEN) ----------
template <int H, int OUT>
__global__ void __launch_bounds__(256, 6)
spmm_warp(const __half* __restrict__ x,
          float* __restrict__ yf,
          __half* __restrict__ yh,
          const int* __restrict__ cols,
          const float* __restrict__ vals,
          const float* __restrict__ bias) {
    constexpr int PER = H / 32;
    constexpr int UNR = (PER == 8) ? 4 : 8;
    const int lane = threadIdx.x & 31;
    const int n = blockIdx.x * 8 + (threadIdx.x >> 5);
    if (n >= N_NODES) return;

    int e  = g_rowptr[n];
    const int e1 = g_rowptr[n + 1];

    float acc[PER];
#pragma unroll
    for (int k = 0; k < PER; k++) acc[k] = 0.f;

    for (; e + 32 <= e1; e += 32) {
        int   c = __ldg(cols + e + lane);
        float v = __ldg(vals + e + lane);
#pragma unroll UNR
        for (int j = 0; j < 32; j++) {
            int   cj = __shfl_sync(0xffffffffu, c, j);
            float vj = __shfl_sync(0xffffffffu, v, j);
            if (PER == 8) {
                uint4 q = __ldg(reinterpret_cast<const uint4*>(x) +
                                (size_t)cj * (H / 8) + lane);
                float2 f0 = h2f2(q.x), f1 = h2f2(q.y), f2 = h2f2(q.z), f3 = h2f2(q.w);
                acc[0] += vj * f0.x; acc[1] += vj * f0.y;
                acc[2] += vj * f1.x; acc[3] += vj * f1.y;
                acc[4 % PER] += vj * f2.x; acc[5 % PER] += vj * f2.y;
                acc[6 % PER] += vj * f3.x; acc[7 % PER] += vj * f3.y;
            } else {
                uint2 q = __ldg(reinterpret_cast<const uint2*>(x) +
                                (size_t)cj * (H / 4) + lane);
                float2 f0 = h2f2(q.x), f1 = h2f2(q.y);
                acc[0] += vj * f0.x; acc[1] += vj * f0.y;
                acc[2 % PER] += vj * f1.x; acc[3 % PER] += vj * f1.y;
            }
        }
    }
    int rem = e1 - e;
    if (rem > 0) {
        int   c = (lane < rem) ? __ldg(cols + e + lane) : 0;
        float v = (lane < rem) ? __ldg(vals + e + lane) : 0.f;
        for (int j = 0; j < rem; j++) {
            int   cj = __shfl_sync(0xffffffffu, c, j);
            float vj = __shfl_sync(0xffffffffu, v, j);
            if (PER == 8) {
                uint4 q = __ldg(reinterpret_cast<const uint4*>(x) +
                                (size_t)cj * (H / 8) + lane);
                float2 f0 = h2f2(q.x), f1 = h2f2(q.y), f2 = h2f2(q.z), f3 = h2f2(q.w);
                acc[0] += vj * f0.x; acc[1] += vj * f0.y;
                acc[2] += vj * f1.x; acc[3] += vj * f1.y;
                acc[4 % PER] += vj * f2.x; acc[5 % PER] += vj * f2.y;
                acc[6 % PER] += vj * f3.x; acc[7 % PER] += vj * f3.y;
            } else {
                uint2 q = __ldg(reinterpret_cast<const uint2*>(x) +
                                (size_t)cj * (H / 4) + lane);
                float2 f0 = h2f2(q.x), f1 = h2f2(q.y);
                acc[0] += vj * f0.x; acc[1] += vj * f0.y;
                acc[2 % PER] += vj * f1.x; acc[3 % PER] += vj * f1.y;
            }
        }
    }

    if (OUT == 0) {
#pragma unroll
        for (int k = 0; k < PER; k++)
            if (bias) acc[k] += __ldg(bias + lane * PER + k);
#pragma unroll
        for (int k = 0; k < PER; k += 4) {
            float4 o = make_float4(acc[k], acc[k + 1],
                                   acc[(k + 2) % PER], acc[(k + 3) % PER]);
            *reinterpret_cast<float4*>(yf + (size_t)n * H + lane * PER + k) = o;
        }
    } else {
        uint32_t p[PER / 2];
#pragma unroll
        for (int k = 0; k < PER / 2; k++)
            p[k] = pkh2(acc[2 * k], acc[2 * k + 1]);
        if (PER == 8) {
            uint4 o = make_uint4(p[0], p[1], p[2 % (PER / 2)], p[3 % (PER / 2)]);
            *reinterpret_cast<uint4*>(yh + (size_t)n * H + lane * 8) = o;
        } else {
            uint2 o = make_uint2(p[0], p[1 % (PER / 2)]);
            *reinterpret_cast<uint2*>(yh + (size_t)n * H + lane * 4) = o;
        }
    }
}

// ===================== HMMA GEMM (fp16 A x fp16-split W, 2 products) ========
// C[M, NTOT] = A[M, KTOT] @ W^T  (W fp16 hi/lo, shape [NTOT, KTOT])
// CTA tile 128(M) x 128(N), 8 warps 4x2, warp tile 32x64,
// *** KC=64 *** (128B smem rows, half the barrier cadence), 2-stage cp.async.
// MODE 1: bias+relu fp16 out.  MODE 3: fp16 out.
// MODE 4: fused feat from z fp32 via pairs; bias+relu, dot Wp2v,
//         atomicAdd into Cf (pre-initialized with bp2).
template <int KTOT, int NTOT, int MODE>
__global__ void __launch_bounds__(256, 2)
gemm_mma(const __half* __restrict__ Ah_,
         const __half* __restrict__ Whi,
         const __half* __restrict__ Wlo,
         float* __restrict__ Cf,
         __half* __restrict__ Ch,
         const float* __restrict__ bias,
         const float* __restrict__ Wp2v,
         const float* __restrict__ zf,
         const int* __restrict__ pairs, int M) {
    constexpr int KC = 64;
    constexpr int NS = KTOT / KC;
    constexpr int ST_A  = 0;                 // 128 rows x 128B = 16 KB
    constexpr int ST_WH = 16384;
    constexpr int ST_WL = 32768;
    constexpr int STAGE = 49152;             // 48 KB

    extern __shared__ __align__(128) char smem[];
    const uint32_t sb = smem_u32(smem);

    const int tid  = threadIdx.x;
    const int lane = tid & 31;
    const int wm   = (tid >> 5) & 3;
    const int wn   = tid >> 7;
    const int m0   = blockIdx.x * 128;
    const int n0   = blockIdx.y * 128;

    // swizzle for 128B rows: chunk c (16B units, 0..7) XOR low-3 row bits
    auto soffs = [](int row, int c) -> uint32_t {
        return (uint32_t)(row * 128 + ((c ^ (row & 7)) << 4));
    };

    auto load_stage = [&](int ks) {
        const int k0 = ks * KC;
        const uint32_t base = sb + (uint32_t)(ks & 1) * STAGE;
        // A: 1024 chunk writes (4 per thread)
#pragma unroll
        for (int i = 0; i < 4; i++) {
            int id  = tid + i * 256;           // 0..1023
            int row = id >> 3;                 // 0..127
            int c   = id & 7;
            uint32_t so = soffs(row, c);
            if (MODE == 4) {
                int p = min(m0 + row, M - 1);
                int kcol = k0 + c * 8;         // global feat column (halves)
                int seg  = kcol >> 7;          // 0=s, 1=d, 2=prod
                int kloc = kcol & 127;
                int s = __ldg(pairs + p);
                int d = __ldg(pairs + N_PAIRS + p);
                uint4 o;
                if (seg == 0) {
                    const float* zp = zf + (size_t)s * EMB + kloc;
                    float4 a0 = *reinterpret_cast<const float4*>(zp);
                    float4 a1 = *reinterpret_cast<const float4*>(zp + 4);
                    o = make_uint4(pkh2(a0.x, a0.y), pkh2(a0.z, a0.w),
                                   pkh2(a1.x, a1.y), pkh2(a1.z, a1.w));
                } else if (seg == 1) {
                    const float* zp = zf + (size_t)d * EMB + kloc;
                    float4 a0 = *reinterpret_cast<const float4*>(zp);
                    float4 a1 = *reinterpret_cast<const float4*>(zp + 4);
                    o = make_uint4(pkh2(a0.x, a0.y), pkh2(a0.z, a0.w),
                                   pkh2(a1.x, a1.y), pkh2(a1.z, a1.w));
                } else {
                    const float* zs = zf + (size_t)s * EMB + kloc;
                    const float* zd = zf + (size_t)d * EMB + kloc;
                    float4 a0 = *reinterpret_cast<const float4*>(zs);
                    float4 a1 = *reinterpret_cast<const float4*>(zs + 4);
                    float4 b0 = *reinterpret_cast<const float4*>(zd);
                    float4 b1 = *reinterpret_cast<const float4*>(zd + 4);
                    o = make_uint4(pkh2(a0.x * b0.x, a0.y * b0.y),
                                   pkh2(a0.z * b0.z, a0.w * b0.w),
                                   pkh2(a1.x * b1.x, a1.y * b1.y),
                                   pkh2(a1.z * b1.z, a1.w * b1.w));
                }
                *reinterpret_cast<uint4*>(smem + (uint32_t)(ks & 1) * STAGE + ST_A + so) = o;
            } else {
                int rowa = min(m0 + row, M - 1);
                cp16(base + ST_A + so, Ah_ + (size_t)rowa * KTOT + k0 + c * 8);
            }
        }
        // W hi/lo: 1024 chunk writes each (4 per thread each)
#pragma unroll
        for (int i = 0; i < 4; i++) {
            int id  = tid + i * 256;
            int row = id >> 3;
            int c   = id & 7;
            uint32_t so = soffs(row, c);
            size_t goff = (size_t)(n0 + row) * KTOT + k0 + c * 8;
            cp16(base + ST_WH + so, Whi + goff);
            cp16(base + ST_WL + so, Wlo + goff);
        }
    };

    float acc[2][8][4];
#pragma unroll
    for (int a = 0; a < 2; a++)
#pragma unroll
        for (int b = 0; b < 8; b++)
#pragma unroll
            for (int c = 0; c < 4; c++) acc[a][b][c] = 0.f;

    const int lrow  = (lane & 7) + ((lane >> 3) & 1) * 8;
    const int khalf = lane >> 4;

    load_stage(0);
    CP_COMMIT();
    if (MODE == 4) __syncthreads();

    for (int ks = 0; ks < NS; ks++) {
        if (ks + 1 < NS) load_stage(ks + 1);
        CP_COMMIT();
        CP_WAIT1();
        __syncthreads();

        const uint32_t base = sb + (uint32_t)(ks & 1) * STAGE;
#pragma unroll
        for (int kk = 0; kk < 4; kk++) {
            const int c = kk * 2 + khalf;      // 0..7
            uint32_t ah[2][4];
#pragma unroll
            for (int mi = 0; mi < 2; mi++) {
                int row = wm * 32 + mi * 16 + lrow;
                ldsm4(ah[mi][0], ah[mi][1], ah[mi][2], ah[mi][3],
                      base + ST_A + soffs(row, c));
            }
            uint32_t bh[4][4], bl[4][4];
#pragma unroll
            for (int ng = 0; ng < 4; ng++) {
                int row = wn * 64 + ng * 16 + lrow;
                uint32_t so = soffs(row, c);
                ldsm4(bh[ng][0], bh[ng][1], bh[ng][2], bh[ng][3], base + ST_WH + so);
                ldsm4(bl[ng][0], bl[ng][1], bl[ng][2], bl[ng][3], base + ST_WL + so);
            }
#pragma unroll
            for (int mi = 0; mi < 2; mi++)
#pragma unroll
                for (int ng = 0; ng < 4; ng++)
#pragma unroll
                    for (int sub = 0; sub < 2; sub++) {
                        int ni = ng * 2 + sub;
                        float* d = acc[mi][ni];
                        mma_h(d[0], d[1], d[2], d[3],
                              ah[mi][0], ah[mi][1], ah[mi][2], ah[mi][3],
                              bh[ng][sub], bh[ng][sub + 2]);
                        mma_h(d[0], d[1], d[2], d[3],
                              ah[mi][0], ah[mi][1], ah[mi][2], ah[mi][3],
                              bl[ng][sub], bl[ng][sub + 2]);
                    }
        }
        __syncthreads();
    }

    // ---- epilogue ----
    if (MODE == 4) {
#pragma unroll
        for (int mi = 0; mi < 2; mi++) {
            float s0 = 0.f, s1 = 0.f;
#pragma unroll
            for (int ni = 0; ni < 8; ni++) {
                int col = n0 + wn * 64 + ni * 8 + 2 * (lane & 3);
                float b0 = __ldg(bias + col),  b1 = __ldg(bias + col + 1);
                float w0 = __ldg(Wp2v + col),  w1 = __ldg(Wp2v + col + 1);
                s0 += fmaxf(acc[mi][ni][0] + b0, 0.f) * w0
                    + fmaxf(acc[mi][ni][1] + b1, 0.f) * w1;
                s1 += fmaxf(acc[mi][ni][2] + b0, 0.f) * w0
                    + fmaxf(acc[mi][ni][3] + b1, 0.f) * w1;
            }
            s0 += __shfl_xor_sync(0xffffffffu, s0, 1);
            s0 += __shfl_xor_sync(0xffffffffu, s0, 2);
            s1 += __shfl_xor_sync(0xffffffffu, s1, 1);
            s1 += __shfl_xor_sync(0xffffffffu, s1, 2);
            if ((lane & 3) == 0) {
                int r0 = m0 + wm * 32 + mi * 16 + (lane >> 2);
                int r1 = r0 + 8;
                if (r0 < M) atomicAdd(Cf + r0, s0);
                if (r1 < M) atomicAdd(Cf + r1, s1);
            }
        }
        return;
    }
#pragma unroll
    for (int mi = 0; mi < 2; mi++) {
        int r0 = m0 + wm * 32 + mi * 16 + (lane >> 2);
        int r1 = r0 + 8;
#pragma unroll
        for (int ni = 0; ni < 8; ni++) {
            int col = n0 + wn * 64 + ni * 8 + 2 * (lane & 3);
            float v0 = acc[mi][ni][0], v1 = acc[mi][ni][1];
            float v2 = acc[mi][ni][2], v3 = acc[mi][ni][3];
            if (MODE == 1) {
                float b0 = __ldg(bias + col), b1 = __ldg(bias + col + 1);
                v0 = fmaxf(v0 + b0, 0.f); v1 = fmaxf(v1 + b1, 0.f);
                v2 = fmaxf(v2 + b0, 0.f); v3 = fmaxf(v3 + b1, 0.f);
            }
            if (r0 < M)
                *reinterpret_cast<uint32_t*>(Ch + (size_t)r0 * NTOT + col) = pkh2(v0, v1);
            if (r1 < M)
                *reinterpret_cast<uint32_t*>(Ch + (size_t)r1 * NTOT + col) = pkh2(v2, v3);
        }
    }
}

// ===========================================================================
extern "C" void kernel_launch(void* const* d_in, const int* in_sizes, int n_in,
                              void* d_out, int out_size) {
    const int*   tids     = (const int*)  d_in[0];
    const int*   rows     = (const int*)  d_in[1];
    const int*   cols     = (const int*)  d_in[2];
    const float* vals     = (const float*)d_in[3];
    const int*   pairs    = (const int*)  d_in[4];
    const float* node_emb = (const float*)d_in[5];
    const float* type_emb = (const float*)d_in[6];
    const float* W1  = (const float*)d_in[7];
    const float* b1  = (const float*)d_in[8];
    const float* W2  = (const float*)d_in[9];
    const float* b2  = (const float*)d_in[10];
    const float* Wp1 = (const float*)d_in[11];
    const float* bp1 = (const float*)d_in[12];
    const float* Wp2 = (const float*)d_in[13];
    const float* bp2 = (const float*)d_in[14];
    float* out = (float*)d_out;

    void *pxh, *paxh, *phh, *phwh, *pz;
    void *w1h, *w1l, *w2h, *w2l, *wp1h, *wp1l;
    cudaGetSymbolAddress(&pxh,  g_xh);
    cudaGetSymbolAddress(&paxh, g_axh);
    cudaGetSymbolAddress(&phh,  g_hh);
    cudaGetSymbolAddress(&phwh, g_hwh);
    cudaGetSymbolAddress(&pz,   g_z);
    cudaGetSymbolAddress(&w1h,  g_w1hi);  cudaGetSymbolAddress(&w1l, g_w1lo);
    cudaGetSymbolAddress(&w2h,  g_w2hi);  cudaGetSymbolAddress(&w2l, g_w2lo);
    cudaGetSymbolAddress(&wp1h, g_wp1hi); cudaGetSymbolAddress(&wp1l, g_wp1lo);

    constexpr int SMEM = 2 * 49152;   // 96 KB (2-stage, KC=64)
    cudaFuncSetAttribute(gemm_mma<256, 256, 1>,
                         cudaFuncAttributeMaxDynamicSharedMemorySize, SMEM);
    cudaFuncSetAttribute(gemm_mma<256, 128, 3>,
                         cudaFuncAttributeMaxDynamicSharedMemorySize, SMEM);
    cudaFuncSetAttribute(gemm_mma<384, 128, 4>,
                         cudaFuncAttributeMaxDynamicSharedMemorySize, SMEM);

    // 0. weight prep (one launch, transpose + fp16 split)
    {
        int tot = HID * HID + HID * EMB + 3 * EMB * EMB;
        prep_w_all<<<(tot + 255) / 256, 256>>>(W1, W2, Wp1);
    }
    // 1. row_ptr (edge-boundary scatter)
    build_rowptr<<<(N_EDGES + 255) / 256, 256>>>(rows);
    // 2. x = fp16(node_emb + type_emb[type])
    add_emb<<<(N_NODES * HID / 4 + 255) / 256, 256>>>(node_emb, type_emb, tids);
    // 3. ax = spmm(x) -> fp16   [round-10 spmm, frozen]
    spmm_warp<HID, 2><<<(N_NODES + 7) / 8, 256>>>(
        (const __half*)pxh, nullptr, (__half*)paxh, cols, vals, nullptr);
    // 4. h = relu(ax @ W1 + b1) -> fp16   [HMMA 128x128, KC=64]
    {
        dim3 grid((N_NODES + 127) / 128, HID / 128);
        gemm_mma<256, 256, 1><<<grid, 256, SMEM>>>(
            (const __half*)paxh, (const __half*)w1h, (const __half*)w1l,
            nullptr, (__half*)phh, b1, nullptr, nullptr, nullptr, N_NODES);
    }
    // 5. hw = h @ W2 -> fp16   [HMMA 128x128, KC=64]
    {
        dim3 grid((N_NODES + 127) / 128, EMB / 128);
        gemm_mma<256, 128, 3><<<grid, 256, SMEM>>>(
            (const __half*)phh, (const __half*)w2h, (const __half*)w2l,
            nullptr, (__half*)phwh, nullptr, nullptr, nullptr, nullptr, N_NODES);
    }
    // 6. z = spmm(hw) + b2  (fp32)   [round-10 spmm, frozen]
    spmm_warp<EMB, 0><<<(N_NODES + 7) / 8, 256>>>(
        (const __half*)phwh, (float*)pz, nullptr, cols, vals, b2);
    // 7+8. out = relu(feat @ Wp1 + bp1) @ Wp2 + bp2  [fused feat + HMMA + dot]
    init_out<<<(N_PAIRS + 255) / 256, 256>>>(out, bp2);
    {
        dim3 grid((N_PAIRS + 127) / 128, EMB / 128);
        gemm_mma<384, 128, 4><<<grid, 256, SMEM>>>(
            nullptr, (const __half*)wp1h, (const __half*)wp1l,
            out, nullptr, bp1, Wp2, (const float*)pz, pairs, N_PAIRS);
    }
}

// round 15
// speedup vs baseline: 1.3086x; 1.1354x over previous
#include <cuda_runtime.h>
#include <cuda_fp16.h>
#include <cstdint>

#define N_NODES 100000
#define N_EDGES 3200000
#define HID 256
#define EMB 128
#define N_PAIRS 100000

// ===================== scratch (device globals) =============================
__device__ __half g_xh [N_NODES * HID];         // spmm1 input (fp16)
__device__ __half g_axh[N_NODES * HID];         // spmm1 out = GEMM1 A (fp16)
__device__ __half g_hh [N_NODES * HID];         // GEMM1 out = GEMM2 A (fp16)
__device__ __half g_hwh[N_NODES * EMB];         // GEMM2 out (fp16, feeds spmm2)
__device__ float  g_z  [N_NODES * EMB];         // spmm2 out (fp32)
__device__ int    g_rowptr[N_NODES + 1];
// transposed + fp16-split weights: [N][K]
__device__ __half g_w1hi[HID * HID];            // lo unused for GEMM1 (NPROD=1)
__device__ __half g_w2hi[EMB * HID];            // lo unused for GEMM2 (NPROD=1)
__device__ __half g_wp1hi[EMB * 3 * EMB], g_wp1lo[EMB * 3 * EMB];

// ===================== helpers ==============================================
__device__ __forceinline__ uint32_t smem_u32(const void* p) {
    uint32_t a;
    asm("{ .reg .u64 t; cvta.to.shared.u64 t, %1; cvt.u32.u64 %0, t; }"
        : "=r"(a) : "l"(p));
    return a;
}
__device__ __forceinline__ void cp16(uint32_t dst, const void* src) {
    asm volatile("cp.async.cg.shared.global [%0], [%1], 16;" :: "r"(dst), "l"(src));
}
#define CP_COMMIT() asm volatile("cp.async.commit_group;" ::: "memory")
#define CP_WAIT1()  asm volatile("cp.async.wait_group 1;" ::: "memory")

__device__ __forceinline__ void ldsm4(uint32_t& r0, uint32_t& r1,
                                      uint32_t& r2, uint32_t& r3, uint32_t addr) {
    asm volatile("ldmatrix.sync.aligned.m8n8.x4.shared.b16 {%0,%1,%2,%3}, [%4];"
                 : "=r"(r0), "=r"(r1), "=r"(r2), "=r"(r3) : "r"(addr));
}
__device__ __forceinline__ void mma_h(float& d0, float& d1, float& d2, float& d3,
                                      uint32_t a0, uint32_t a1, uint32_t a2, uint32_t a3,
                                      uint32_t b0, uint32_t b1) {
    asm volatile(
        "mma.sync.aligned.m16n8k16.row.col.f32.f16.f16.f32 "
        "{%0,%1,%2,%3}, {%4,%5,%6,%7}, {%8,%9}, {%0,%1,%2,%3};"
        : "+f"(d0), "+f"(d1), "+f"(d2), "+f"(d3)
        : "r"(a0), "r"(a1), "r"(a2), "r"(a3), "r"(b0), "r"(b1));
}
__device__ __forceinline__ void split_h(float v, __half& h, __half& l) {
    h = __float2half(v);
    l = __float2half(v - __half2float(h));
}
__device__ __forceinline__ float2 h2f2(uint32_t u) {
    return __half22float2(*reinterpret_cast<__half2*>(&u));
}
__device__ __forceinline__ uint32_t pkh2(float a, float b) {
    __half2 t = __floats2half2_rn(a, b);
    return *reinterpret_cast<uint32_t*>(&t);
}

// ===================== small kernels ========================================
__global__ void build_rowptr(const int* __restrict__ rows) {
    int e = blockIdx.x * blockDim.x + threadIdx.x;
    if (e >= N_EDGES) return;
    int r  = rows[e];
    int rn = (e + 1 < N_EDGES) ? rows[e + 1] : N_NODES;
    if (e == 0)
        for (int n = 0; n <= r; n++) g_rowptr[n] = 0;
    for (int n = r + 1; n <= rn; n++) g_rowptr[n] = e + 1;
}

__global__ void add_emb(const float* __restrict__ node_emb,
                        const float* __restrict__ type_emb,
                        const int* __restrict__ tids) {
    int i = blockIdx.x * blockDim.x + threadIdx.x;
    const int NV = N_NODES * HID / 4;
    if (i >= NV) return;
    int n  = i / (HID / 4);
    int k4 = i % (HID / 4);
    int t  = tids[n];
    float4 a = reinterpret_cast<const float4*>(node_emb)[i];
    float4 b = reinterpret_cast<const float4*>(type_emb)[t * (HID / 4) + k4];
    reinterpret_cast<uint2*>(g_xh)[i] =
        make_uint2(pkh2(a.x + b.x, a.y + b.y), pkh2(a.z + b.z, a.w + b.w));
}

// W1/W2: hi only.  Wp1: hi+lo split.
__global__ void prep_w_all(const float* __restrict__ W1, const float* __restrict__ W2,
                           const float* __restrict__ Wp1) {
    int i = blockIdx.x * blockDim.x + threadIdx.x;
    const int S1 = HID * HID;
    const int S2 = S1 + HID * EMB;
    const int S3 = S2 + 3 * EMB * EMB;
    if (i < S1) {
        int k = i / HID, n = i % HID;
        g_w1hi[n * HID + k] = __float2half(W1[i]);
    } else if (i < S2) {
        int j = i - S1;
        int k = j / EMB, n = j % EMB;
        g_w2hi[n * HID + k] = __float2half(W2[j]);
    } else if (i < S3) {
        int j = i - S2;
        int k = j / EMB, n = j % EMB;
        __half h, l;
        split_h(Wp1[j], h, l);
        g_wp1hi[n * (3 * EMB) + k] = h;
        g_wp1lo[n * (3 * EMB) + k] = l;
    }
}

__global__ void init_out(float* __restrict__ out, const float* __restrict__ bp2) {
    int i = blockIdx.x * blockDim.x + threadIdx.x;
    if (i < N_PAIRS) out[i] = bp2[0];
}

// ---------------- SpMM: warp-per-node (round-10 structure, FROZEN) ----------
template <int H, int OUT>
__global__ void __launch_bounds__(256, 6)
spmm_warp(const __half* __restrict__ x,
          float* __restrict__ yf,
          __half* __restrict__ yh,
          const int* __restrict__ cols,
          const float* __restrict__ vals,
          const float* __restrict__ bias) {
    constexpr int PER = H / 32;
    constexpr int UNR = (PER == 8) ? 4 : 8;
    const int lane = threadIdx.x & 31;
    const int n = blockIdx.x * 8 + (threadIdx.x >> 5);
    if (n >= N_NODES) return;

    int e  = g_rowptr[n];
    const int e1 = g_rowptr[n + 1];

    float acc[PER];
#pragma unroll
    for (int k = 0; k < PER; k++) acc[k] = 0.f;

    for (; e + 32 <= e1; e += 32) {
        int   c = __ldg(cols + e + lane);
        float v = __ldg(vals + e + lane);
#pragma unroll UNR
        for (int j = 0; j < 32; j++) {
            int   cj = __shfl_sync(0xffffffffu, c, j);
            float vj = __shfl_sync(0xffffffffu, v, j);
            if (PER == 8) {
                uint4 q = __ldg(reinterpret_cast<const uint4*>(x) +
                                (size_t)cj * (H / 8) + lane);
                float2 f0 = h2f2(q.x), f1 = h2f2(q.y), f2 = h2f2(q.z), f3 = h2f2(q.w);
                acc[0] += vj * f0.x; acc[1] += vj * f0.y;
                acc[2] += vj * f1.x; acc[3] += vj * f1.y;
                acc[4 % PER] += vj * f2.x; acc[5 % PER] += vj * f2.y;
                acc[6 % PER] += vj * f3.x; acc[7 % PER] += vj * f3.y;
            } else {
                uint2 q = __ldg(reinterpret_cast<const uint2*>(x) +
                                (size_t)cj * (H / 4) + lane);
                float2 f0 = h2f2(q.x), f1 = h2f2(q.y);
                acc[0] += vj * f0.x; acc[1] += vj * f0.y;
                acc[2 % PER] += vj * f1.x; acc[3 % PER] += vj * f1.y;
            }
        }
    }
    int rem = e1 - e;
    if (rem > 0) {
        int   c = (lane < rem) ? __ldg(cols + e + lane) : 0;
        float v = (lane < rem) ? __ldg(vals + e + lane) : 0.f;
        for (int j = 0; j < rem; j++) {
            int   cj = __shfl_sync(0xffffffffu, c, j);
            float vj = __shfl_sync(0xffffffffu, v, j);
            if (PER == 8) {
                uint4 q = __ldg(reinterpret_cast<const uint4*>(x) +
                                (size_t)cj * (H / 8) + lane);
                float2 f0 = h2f2(q.x), f1 = h2f2(q.y), f2 = h2f2(q.z), f3 = h2f2(q.w);
                acc[0] += vj * f0.x; acc[1] += vj * f0.y;
                acc[2] += vj * f1.x; acc[3] += vj * f1.y;
                acc[4 % PER] += vj * f2.x; acc[5 % PER] += vj * f2.y;
                acc[6 % PER] += vj * f3.x; acc[7 % PER] += vj * f3.y;
            } else {
                uint2 q = __ldg(reinterpret_cast<const uint2*>(x) +
                                (size_t)cj * (H / 4) + lane);
                float2 f0 = h2f2(q.x), f1 = h2f2(q.y);
                acc[0] += vj * f0.x; acc[1] += vj * f0.y;
                acc[2 % PER] += vj * f1.x; acc[3 % PER] += vj * f1.y;
            }
        }
    }

    if (OUT == 0) {
#pragma unroll
        for (int k = 0; k < PER; k++)
            if (bias) acc[k] += __ldg(bias + lane * PER + k);
#pragma unroll
        for (int k = 0; k < PER; k += 4) {
            float4 o = make_float4(acc[k], acc[k + 1],
                                   acc[(k + 2) % PER], acc[(k + 3) % PER]);
            *reinterpret_cast<float4*>(yf + (size_t)n * H + lane * PER + k) = o;
        }
    } else {
        uint32_t p[PER / 2];
#pragma unroll
        for (int k = 0; k < PER / 2; k++)
            p[k] = pkh2(acc[2 * k], acc[2 * k + 1]);
        if (PER == 8) {
            uint4 o = make_uint4(p[0], p[1], p[2 % (PER / 2)], p[3 % (PER / 2)]);
            *reinterpret_cast<uint4*>(yh + (size_t)n * H + lane * 8) = o;
        } else {
            uint2 o = make_uint2(p[0], p[1 % (PER / 2)]);
            *reinterpret_cast<uint2*>(yh + (size_t)n * H + lane * 4) = o;
        }
    }
}

// ===================== HMMA GEMM ============================================
// C[M, NTOT] = A[M, KTOT] @ W^T.  NPROD=2: W split hi+lo (2 MMAs/frag);
// NPROD=1: W hi only (1 MMA/frag, outputs fp16-rounded anyway).
// CTA 128x128, 8 warps 4x2, warp tile 32x64, KC=64, 2-stage cp.async.
// MODE 1: bias+relu fp16 out.  MODE 3: fp16 out.
// MODE 4: fused feat from z fp32 via pairs; bias+relu, dot Wp2v,
//         atomicAdd into Cf (pre-initialized with bp2).
template <int KTOT, int NTOT, int MODE, int NPROD>
__global__ void __launch_bounds__(256, 2)
gemm_mma(const __half* __restrict__ Ah_,
         const __half* __restrict__ Whi,
         const __half* __restrict__ Wlo,
         float* __restrict__ Cf,
         __half* __restrict__ Ch,
         const float* __restrict__ bias,
         const float* __restrict__ Wp2v,
         const float* __restrict__ zf,
         const int* __restrict__ pairs, int M) {
    constexpr int KC = 64;
    constexpr int NS = KTOT / KC;
    constexpr int ST_A  = 0;                           // 16 KB
    constexpr int ST_WH = 16384;
    constexpr int ST_WL = 32768;                       // NPROD=2 only
    constexpr int STAGE = (NPROD == 2) ? 49152 : 32768;

    extern __shared__ __align__(128) char smem[];
    const uint32_t sb = smem_u32(smem);

    const int tid  = threadIdx.x;
    const int lane = tid & 31;
    const int wm   = (tid >> 5) & 3;
    const int wn   = tid >> 7;
    const int m0   = blockIdx.x * 128;
    const int n0   = blockIdx.y * 128;

    auto soffs = [](int row, int c) -> uint32_t {
        return (uint32_t)(row * 128 + ((c ^ (row & 7)) << 4));
    };

    auto load_stage = [&](int ks) {
        const int k0 = ks * KC;
        const uint32_t base = sb + (uint32_t)(ks & 1) * STAGE;
#pragma unroll
        for (int i = 0; i < 4; i++) {
            int id  = tid + i * 256;
            int row = id >> 3;
            int c   = id & 7;
            uint32_t so = soffs(row, c);
            if (MODE == 4) {
                int p = min(m0 + row, M - 1);
                int kcol = k0 + c * 8;
                int seg  = kcol >> 7;
                int kloc = kcol & 127;
                int s = __ldg(pairs + p);
                int d = __ldg(pairs + N_PAIRS + p);
                uint4 o;
                if (seg == 0) {
                    const float* zp = zf + (size_t)s * EMB + kloc;
                    float4 a0 = *reinterpret_cast<const float4*>(zp);
                    float4 a1 = *reinterpret_cast<const float4*>(zp + 4);
                    o = make_uint4(pkh2(a0.x, a0.y), pkh2(a0.z, a0.w),
                                   pkh2(a1.x, a1.y), pkh2(a1.z, a1.w));
                } else if (seg == 1) {
                    const float* zp = zf + (size_t)d * EMB + kloc;
                    float4 a0 = *reinterpret_cast<const float4*>(zp);
                    float4 a1 = *reinterpret_cast<const float4*>(zp + 4);
                    o = make_uint4(pkh2(a0.x, a0.y), pkh2(a0.z, a0.w),
                                   pkh2(a1.x, a1.y), pkh2(a1.z, a1.w));
                } else {
                    const float* zs = zf + (size_t)s * EMB + kloc;
                    const float* zd = zf + (size_t)d * EMB + kloc;
                    float4 a0 = *reinterpret_cast<const float4*>(zs);
                    float4 a1 = *reinterpret_cast<const float4*>(zs + 4);
                    float4 b0 = *reinterpret_cast<const float4*>(zd);
                    float4 b1 = *reinterpret_cast<const float4*>(zd + 4);
                    o = make_uint4(pkh2(a0.x * b0.x, a0.y * b0.y),
                                   pkh2(a0.z * b0.z, a0.w * b0.w),
                                   pkh2(a1.x * b1.x, a1.y * b1.y),
                                   pkh2(a1.z * b1.z, a1.w * b1.w));
                }
                *reinterpret_cast<uint4*>(smem + (uint32_t)(ks & 1) * STAGE + ST_A + so) = o;
            } else {
                int rowa = min(m0 + row, M - 1);
                cp16(base + ST_A + so, Ah_ + (size_t)rowa * KTOT + k0 + c * 8);
            }
        }
#pragma unroll
        for (int i = 0; i < 4; i++) {
            int id  = tid + i * 256;
            int row = id >> 3;
            int c   = id & 7;
            uint32_t so = soffs(row, c);
            size_t goff = (size_t)(n0 + row) * KTOT + k0 + c * 8;
            cp16(base + ST_WH + so, Whi + goff);
            if (NPROD == 2) cp16(base + ST_WL + so, Wlo + goff);
        }
    };

    float acc[2][8][4];
#pragma unroll
    for (int a = 0; a < 2; a++)
#pragma unroll
        for (int b = 0; b < 8; b++)
#pragma unroll
            for (int c = 0; c < 4; c++) acc[a][b][c] = 0.f;

    const int lrow  = (lane & 7) + ((lane >> 3) & 1) * 8;
    const int khalf = lane >> 4;

    load_stage(0);
    CP_COMMIT();
    if (MODE == 4) __syncthreads();

    for (int ks = 0; ks < NS; ks++) {
        if (ks + 1 < NS) load_stage(ks + 1);
        CP_COMMIT();
        CP_WAIT1();
        __syncthreads();

        const uint32_t base = sb + (uint32_t)(ks & 1) * STAGE;
#pragma unroll
        for (int kk = 0; kk < 4; kk++) {
            const int c = kk * 2 + khalf;
            uint32_t ah[2][4];
#pragma unroll
            for (int mi = 0; mi < 2; mi++) {
                int row = wm * 32 + mi * 16 + lrow;
                ldsm4(ah[mi][0], ah[mi][1], ah[mi][2], ah[mi][3],
                      base + ST_A + soffs(row, c));
            }
            uint32_t bh[4][4], bl[4][4];
#pragma unroll
            for (int ng = 0; ng < 4; ng++) {
                int row = wn * 64 + ng * 16 + lrow;
                uint32_t so = soffs(row, c);
                ldsm4(bh[ng][0], bh[ng][1], bh[ng][2], bh[ng][3], base + ST_WH + so);
                if (NPROD == 2)
                    ldsm4(bl[ng][0], bl[ng][1], bl[ng][2], bl[ng][3], base + ST_WL + so);
            }
#pragma unroll
            for (int mi = 0; mi < 2; mi++)
#pragma unroll
                for (int ng = 0; ng < 4; ng++)
#pragma unroll
                    for (int sub = 0; sub < 2; sub++) {
                        int ni = ng * 2 + sub;
                        float* d = acc[mi][ni];
                        mma_h(d[0], d[1], d[2], d[3],
                              ah[mi][0], ah[mi][1], ah[mi][2], ah[mi][3],
                              bh[ng][sub], bh[ng][sub + 2]);
                        if (NPROD == 2)
                            mma_h(d[0], d[1], d[2], d[3],
                                  ah[mi][0], ah[mi][1], ah[mi][2], ah[mi][3],
                                  bl[ng][sub], bl[ng][sub + 2]);
                    }
        }
        __syncthreads();
    }

    // ---- epilogue ----
    if (MODE == 4) {
#pragma unroll
        for (int mi = 0; mi < 2; mi++) {
            float s0 = 0.f, s1 = 0.f;
#pragma unroll
            for (int ni = 0; ni < 8; ni++) {
                int col = n0 + wn * 64 + ni * 8 + 2 * (lane & 3);
                float b0 = __ldg(bias + col),  b1 = __ldg(bias + col + 1);
                float w0 = __ldg(Wp2v + col),  w1 = __ldg(Wp2v + col + 1);
                s0 += fmaxf(acc[mi][ni][0] + b0, 0.f) * w0
                    + fmaxf(acc[mi][ni][1] + b1, 0.f) * w1;
                s1 += fmaxf(acc[mi][ni][2] + b0, 0.f) * w0
                    + fmaxf(acc[mi][ni][3] + b1, 0.f) * w1;
            }
            s0 += __shfl_xor_sync(0xffffffffu, s0, 1);
            s0 += __shfl_xor_sync(0xffffffffu, s0, 2);
            s1 += __shfl_xor_sync(0xffffffffu, s1, 1);
            s1 += __shfl_xor_sync(0xffffffffu, s1, 2);
            if ((lane & 3) == 0) {
                int r0 = m0 + wm * 32 + mi * 16 + (lane >> 2);
                int r1 = r0 + 8;
                if (r0 < M) atomicAdd(Cf + r0, s0);
                if (r1 < M) atomicAdd(Cf + r1, s1);
            }
        }
        return;
    }
#pragma unroll
    for (int mi = 0; mi < 2; mi++) {
        int r0 = m0 + wm * 32 + mi * 16 + (lane >> 2);
        int r1 = r0 + 8;
#pragma unroll
        for (int ni = 0; ni < 8; ni++) {
            int col = n0 + wn * 64 + ni * 8 + 2 * (lane & 3);
            float v0 = acc[mi][ni][0], v1 = acc[mi][ni][1];
            float v2 = acc[mi][ni][2], v3 = acc[mi][ni][3];
            if (MODE == 1) {
                float b0 = __ldg(bias + col), b1 = __ldg(bias + col + 1);
                v0 = fmaxf(v0 + b0, 0.f); v1 = fmaxf(v1 + b1, 0.f);
                v2 = fmaxf(v2 + b0, 0.f); v3 = fmaxf(v3 + b1, 0.f);
            }
            if (r0 < M)
                *reinterpret_cast<uint32_t*>(Ch + (size_t)r0 * NTOT + col) = pkh2(v0, v1);
            if (r1 < M)
                *reinterpret_cast<uint32_t*>(Ch + (size_t)r1 * NTOT + col) = pkh2(v2, v3);
        }
    }
}

// ===========================================================================
extern "C" void kernel_launch(void* const* d_in, const int* in_sizes, int n_in,
                              void* d_out, int out_size) {
    const int*   tids     = (const int*)  d_in[0];
    const int*   rows     = (const int*)  d_in[1];
    const int*   cols     = (const int*)  d_in[2];
    const float* vals     = (const float*)d_in[3];
    const int*   pairs    = (const int*)  d_in[4];
    const float* node_emb = (const float*)d_in[5];
    const float* type_emb = (const float*)d_in[6];
    const float* W1  = (const float*)d_in[7];
    const float* b1  = (const float*)d_in[8];
    const float* W2  = (const float*)d_in[9];
    const float* b2  = (const float*)d_in[10];
    const float* Wp1 = (const float*)d_in[11];
    const float* bp1 = (const float*)d_in[12];
    const float* Wp2 = (const float*)d_in[13];
    const float* bp2 = (const float*)d_in[14];
    float* out = (float*)d_out;

    void *pxh, *paxh, *phh, *phwh, *pz;
    void *w1h, *w2h, *wp1h, *wp1l;
    cudaGetSymbolAddress(&pxh,  g_xh);
    cudaGetSymbolAddress(&paxh, g_axh);
    cudaGetSymbolAddress(&phh,  g_hh);
    cudaGetSymbolAddress(&phwh, g_hwh);
    cudaGetSymbolAddress(&pz,   g_z);
    cudaGetSymbolAddress(&w1h,  g_w1hi);
    cudaGetSymbolAddress(&w2h,  g_w2hi);
    cudaGetSymbolAddress(&wp1h, g_wp1hi); cudaGetSymbolAddress(&wp1l, g_wp1lo);

    constexpr int SMEM1 = 2 * 32768;   // 64 KB (NPROD=1)
    constexpr int SMEM2 = 2 * 49152;   // 96 KB (NPROD=2)
    cudaFuncSetAttribute(gemm_mma<256, 256, 1, 1>,
                         cudaFuncAttributeMaxDynamicSharedMemorySize, SMEM1);
    cudaFuncSetAttribute(gemm_mma<256, 128, 3, 1>,
                         cudaFuncAttributeMaxDynamicSharedMemorySize, SMEM1);
    cudaFuncSetAttribute(gemm_mma<384, 128, 4, 2>,
                         cudaFuncAttributeMaxDynamicSharedMemorySize, SMEM2);

    // 0. weight prep
    {
        int tot = HID * HID + HID * EMB + 3 * EMB * EMB;
        prep_w_all<<<(tot + 255) / 256, 256>>>(W1, W2, Wp1);
    }
    // 1. row_ptr
    build_rowptr<<<(N_EDGES + 255) / 256, 256>>>(rows);
    // 2. x = fp16(node_emb + type_emb[type])
    add_emb<<<(N_NODES * HID / 4 + 255) / 256, 256>>>(node_emb, type_emb, tids);
    // 3. ax = spmm(x) -> fp16
    spmm_warp<HID, 2><<<(N_NODES + 7) / 8, 256>>>(
        (const __half*)pxh, nullptr, (__half*)paxh, cols, vals, nullptr);
    // 4. h = relu(ax @ W1 + b1) -> fp16   [HMMA, 1-product]
    {
        dim3 grid((N_NODES + 127) / 128, HID / 128);
        gemm_mma<256, 256, 1, 1><<<grid, 256, SMEM1>>>(
            (const __half*)paxh, (const __half*)w1h, nullptr,
            nullptr, (__half*)phh, b1, nullptr, nullptr, nullptr, N_NODES);
    }
    // 5. hw = h @ W2 -> fp16   [HMMA, 1-product]
    {
        dim3 grid((N_NODES + 127) / 128, EMB / 128);
        gemm_mma<256, 128, 3, 1><<<grid, 256, SMEM1>>>(
            (const __half*)phh, (const __half*)w2h, nullptr,
            nullptr, (__half*)phwh, nullptr, nullptr, nullptr, nullptr, N_NODES);
    }
    // 6. z = spmm(hw) + b2  (fp32)
    spmm_warp<EMB, 0><<<(N_NODES + 7) / 8, 256>>>(
        (const __half*)phwh, (float*)pz, nullptr, cols, vals, b2);
    // 7+8. out = relu(feat @ Wp1 + bp1) @ Wp2 + bp2  [fused, 2-product]
    init_out<<<(N_PAIRS + 255) / 256, 256>>>(out, bp2);
    {
        dim3 grid((N_PAIRS + 127) / 128, EMB / 128);
        gemm_mma<384, 128, 4, 2><<<grid, 256, SMEM2>>>(
            nullptr, (const __half*)wp1h, (const __half*)wp1l,
            out, nullptr, bp1, Wp2, (const float*)pz, pairs, N_PAIRS);
    }
}

// round 16
// speedup vs baseline: 1.4366x; 1.0978x over previous
#include <cuda_runtime.h>
#include <cuda_fp16.h>
#include <cstdint>

#define N_NODES 100000
#define N_EDGES 3200000
#define HID 256
#define EMB 128
#define N_PAIRS 100000

// ===================== scratch (device globals) =============================
__device__ __half g_xh [N_NODES * HID];         // spmm1 input (fp16)
__device__ __half g_axh[N_NODES * HID];         // spmm1 out = GEMM1 A (fp16)
__device__ __half g_hh [N_NODES * HID];         // GEMM1 out = GEMM2 A (fp16)
__device__ __half g_hwh[N_NODES * EMB];         // GEMM2 out (fp16, feeds spmm2)
__device__ __half g_zh [N_NODES * EMB];         // spmm2 out (fp16, feeds GEMM3)
__device__ int    g_rowptr[N_NODES + 1];
// transposed fp16 weights: [N][K]
__device__ __half g_w1hi[HID * HID];
__device__ __half g_w2hi[EMB * HID];
__device__ __half g_wp1hi[EMB * 3 * EMB];

// ===================== helpers ==============================================
__device__ __forceinline__ uint32_t smem_u32(const void* p) {
    uint32_t a;
    asm("{ .reg .u64 t; cvta.to.shared.u64 t, %1; cvt.u32.u64 %0, t; }"
        : "=r"(a) : "l"(p));
    return a;
}
__device__ __forceinline__ void cp16(uint32_t dst, const void* src) {
    asm volatile("cp.async.cg.shared.global [%0], [%1], 16;" :: "r"(dst), "l"(src));
}
#define CP_COMMIT() asm volatile("cp.async.commit_group;" ::: "memory")
#define CP_WAIT1()  asm volatile("cp.async.wait_group 1;" ::: "memory")

__device__ __forceinline__ void ldsm4(uint32_t& r0, uint32_t& r1,
                                      uint32_t& r2, uint32_t& r3, uint32_t addr) {
    asm volatile("ldmatrix.sync.aligned.m8n8.x4.shared.b16 {%0,%1,%2,%3}, [%4];"
                 : "=r"(r0), "=r"(r1), "=r"(r2), "=r"(r3) : "r"(addr));
}
__device__ __forceinline__ void mma_h(float& d0, float& d1, float& d2, float& d3,
                                      uint32_t a0, uint32_t a1, uint32_t a2, uint32_t a3,
                                      uint32_t b0, uint32_t b1) {
    asm volatile(
        "mma.sync.aligned.m16n8k16.row.col.f32.f16.f16.f32 "
        "{%0,%1,%2,%3}, {%4,%5,%6,%7}, {%8,%9}, {%0,%1,%2,%3};"
        : "+f"(d0), "+f"(d1), "+f"(d2), "+f"(d3)
        : "r"(a0), "r"(a1), "r"(a2), "r"(a3), "r"(b0), "r"(b1));
}
__device__ __forceinline__ float2 h2f2(uint32_t u) {
    return __half22float2(*reinterpret_cast<__half2*>(&u));
}
__device__ __forceinline__ uint32_t pkh2(float a, float b) {
    __half2 t = __floats2half2_rn(a, b);
    return *reinterpret_cast<uint32_t*>(&t);
}

// ===================== small kernels ========================================
__global__ void build_rowptr(const int* __restrict__ rows) {
    int e = blockIdx.x * blockDim.x + threadIdx.x;
    if (e >= N_EDGES) return;
    int r  = rows[e];
    int rn = (e + 1 < N_EDGES) ? rows[e + 1] : N_NODES;
    if (e == 0)
        for (int n = 0; n <= r; n++) g_rowptr[n] = 0;
    for (int n = r + 1; n <= rn; n++) g_rowptr[n] = e + 1;
}

__global__ void add_emb(const float* __restrict__ node_emb,
                        const float* __restrict__ type_emb,
                        const int* __restrict__ tids) {
    int i = blockIdx.x * blockDim.x + threadIdx.x;
    const int NV = N_NODES * HID / 4;
    if (i >= NV) return;
    int n  = i / (HID / 4);
    int k4 = i % (HID / 4);
    int t  = tids[n];
    float4 a = reinterpret_cast<const float4*>(node_emb)[i];
    float4 b = reinterpret_cast<const float4*>(type_emb)[t * (HID / 4) + k4];
    reinterpret_cast<uint2*>(g_xh)[i] =
        make_uint2(pkh2(a.x + b.x, a.y + b.y), pkh2(a.z + b.z, a.w + b.w));
}

// all weights -> transposed fp16 (hi only)
__global__ void prep_w_all(const float* __restrict__ W1, const float* __restrict__ W2,
                           const float* __restrict__ Wp1) {
    int i = blockIdx.x * blockDim.x + threadIdx.x;
    const int S1 = HID * HID;
    const int S2 = S1 + HID * EMB;
    const int S3 = S2 + 3 * EMB * EMB;
    if (i < S1) {
        int k = i / HID, n = i % HID;
        g_w1hi[n * HID + k] = __float2half(W1[i]);
    } else if (i < S2) {
        int j = i - S1;
        int k = j / EMB, n = j % EMB;
        g_w2hi[n * HID + k] = __float2half(W2[j]);
    } else if (i < S3) {
        int j = i - S2;
        int k = j / EMB, n = j % EMB;
        g_wp1hi[n * (3 * EMB) + k] = __float2half(Wp1[j]);
    }
}

__global__ void init_out(float* __restrict__ out, const float* __restrict__ bp2) {
    int i = blockIdx.x * blockDim.x + threadIdx.x;
    if (i < N_PAIRS) out[i] = bp2[0];
}

// ---------------- SpMM: warp-per-node (round-10 structure, FROZEN) ----------
// OUT: 0 = fp32 (+bias), 2 = fp16 (+bias added in fp32 before rounding).
template <int H, int OUT>
__global__ void __launch_bounds__(256, 6)
spmm_warp(const __half* __restrict__ x,
          float* __restrict__ yf,
          __half* __restrict__ yh,
          const int* __restrict__ cols,
          const float* __restrict__ vals,
          const float* __restrict__ bias) {
    constexpr int PER = H / 32;
    constexpr int UNR = (PER == 8) ? 4 : 8;
    const int lane = threadIdx.x & 31;
    const int n = blockIdx.x * 8 + (threadIdx.x >> 5);
    if (n >= N_NODES) return;

    int e  = g_rowptr[n];
    const int e1 = g_rowptr[n + 1];

    float acc[PER];
#pragma unroll
    for (int k = 0; k < PER; k++) acc[k] = 0.f;

    for (; e + 32 <= e1; e += 32) {
        int   c = __ldg(cols + e + lane);
        float v = __ldg(vals + e + lane);
#pragma unroll UNR
        for (int j = 0; j < 32; j++) {
            int   cj = __shfl_sync(0xffffffffu, c, j);
            float vj = __shfl_sync(0xffffffffu, v, j);
            if (PER == 8) {
                uint4 q = __ldg(reinterpret_cast<const uint4*>(x) +
                                (size_t)cj * (H / 8) + lane);
                float2 f0 = h2f2(q.x), f1 = h2f2(q.y), f2 = h2f2(q.z), f3 = h2f2(q.w);
                acc[0] += vj * f0.x; acc[1] += vj * f0.y;
                acc[2] += vj * f1.x; acc[3] += vj * f1.y;
                acc[4 % PER] += vj * f2.x; acc[5 % PER] += vj * f2.y;
                acc[6 % PER] += vj * f3.x; acc[7 % PER] += vj * f3.y;
            } else {
                uint2 q = __ldg(reinterpret_cast<const uint2*>(x) +
                                (size_t)cj * (H / 4) + lane);
                float2 f0 = h2f2(q.x), f1 = h2f2(q.y);
                acc[0] += vj * f0.x; acc[1] += vj * f0.y;
                acc[2 % PER] += vj * f1.x; acc[3 % PER] += vj * f1.y;
            }
        }
    }
    int rem = e1 - e;
    if (rem > 0) {
        int   c = (lane < rem) ? __ldg(cols + e + lane) : 0;
        float v = (lane < rem) ? __ldg(vals + e + lane) : 0.f;
        for (int j = 0; j < rem; j++) {
            int   cj = __shfl_sync(0xffffffffu, c, j);
            float vj = __shfl_sync(0xffffffffu, v, j);
            if (PER == 8) {
                uint4 q = __ldg(reinterpret_cast<const uint4*>(x) +
                                (size_t)cj * (H / 8) + lane);
                float2 f0 = h2f2(q.x), f1 = h2f2(q.y), f2 = h2f2(q.z), f3 = h2f2(q.w);
                acc[0] += vj * f0.x; acc[1] += vj * f0.y;
                acc[2] += vj * f1.x; acc[3] += vj * f1.y;
                acc[4 % PER] += vj * f2.x; acc[5 % PER] += vj * f2.y;
                acc[6 % PER] += vj * f3.x; acc[7 % PER] += vj * f3.y;
            } else {
                uint2 q = __ldg(reinterpret_cast<const uint2*>(x) +
                                (size_t)cj * (H / 4) + lane);
                float2 f0 = h2f2(q.x), f1 = h2f2(q.y);
                acc[0] += vj * f0.x; acc[1] += vj * f0.y;
                acc[2 % PER] += vj * f1.x; acc[3 % PER] += vj * f1.y;
            }
        }
    }

    if (OUT == 0) {
#pragma unroll
        for (int k = 0; k < PER; k++)
            if (bias) acc[k] += __ldg(bias + lane * PER + k);
#pragma unroll
        for (int k = 0; k < PER; k += 4) {
            float4 o = make_float4(acc[k], acc[k + 1],
                                   acc[(k + 2) % PER], acc[(k + 3) % PER]);
            *reinterpret_cast<float4*>(yf + (size_t)n * H + lane * PER + k) = o;
        }
    } else {
        if (bias) {
#pragma unroll
            for (int k = 0; k < PER; k++)
                acc[k] += __ldg(bias + lane * PER + k);
        }
        uint32_t p[PER / 2];
#pragma unroll
        for (int k = 0; k < PER / 2; k++)
            p[k] = pkh2(acc[2 * k], acc[2 * k + 1]);
        if (PER == 8) {
            uint4 o = make_uint4(p[0], p[1], p[2 % (PER / 2)], p[3 % (PER / 2)]);
            *reinterpret_cast<uint4*>(yh + (size_t)n * H + lane * 8) = o;
        } else {
            uint2 o = make_uint2(p[0], p[1 % (PER / 2)]);
            *reinterpret_cast<uint2*>(yh + (size_t)n * H + lane * 4) = o;
        }
    }
}

// ===================== HMMA GEMM (fp16, 1-product) ==========================
// C[M, NTOT] = A[M, KTOT] @ W^T.  CTA 128x128, 8 warps 4x2, warp tile 32x64,
// KC=64, 2-stage cp.async.
// MODE 1: bias+relu fp16 out.  MODE 3: fp16 out.
// MODE 4: fused feat from fp16 z via pairs (seg0/1: async 16B gathers;
//         seg2: product of fp16 z values); bias+relu, dot Wp2v,
//         atomicAdd into Cf (pre-initialized with bp2).
template <int KTOT, int NTOT, int MODE>
__global__ void __launch_bounds__(256, 2)
gemm_mma(const __half* __restrict__ Ah_,
         const __half* __restrict__ Whi,
         float* __restrict__ Cf,
         __half* __restrict__ Ch,
         const float* __restrict__ bias,
         const float* __restrict__ Wp2v,
         const __half* __restrict__ zf,
         const int* __restrict__ pairs, int M) {
    constexpr int KC = 64;
    constexpr int NS = KTOT / KC;
    constexpr int ST_A  = 0;                 // 16 KB
    constexpr int ST_WH = 16384;             // 16 KB
    constexpr int STAGE = 32768;

    extern __shared__ __align__(128) char smem[];
    const uint32_t sb = smem_u32(smem);

    const int tid  = threadIdx.x;
    const int lane = tid & 31;
    const int wm   = (tid >> 5) & 3;
    const int wn   = tid >> 7;
    const int m0   = blockIdx.x * 128;
    const int n0   = blockIdx.y * 128;

    auto soffs = [](int row, int c) -> uint32_t {
        return (uint32_t)(row * 128 + ((c ^ (row & 7)) << 4));
    };

    auto load_stage = [&](int ks) {
        const int k0 = ks * KC;
        const uint32_t base = sb + (uint32_t)(ks & 1) * STAGE;
#pragma unroll
        for (int i = 0; i < 4; i++) {
            int id  = tid + i * 256;
            int row = id >> 3;
            int c   = id & 7;
            uint32_t so = soffs(row, c);
            if (MODE == 4) {
                int p = min(m0 + row, M - 1);
                int kcol = k0 + c * 8;         // global feat column (halves)
                int seg  = kcol >> 7;          // 0=s, 1=d, 2=prod
                int kloc = kcol & 127;
                int s = __ldg(pairs + p);
                int d = __ldg(pairs + N_PAIRS + p);
                if (seg == 0) {
                    cp16(base + ST_A + so, zf + (size_t)s * EMB + kloc);
                } else if (seg == 1) {
                    cp16(base + ST_A + so, zf + (size_t)d * EMB + kloc);
                } else {
                    uint4 qa = *reinterpret_cast<const uint4*>(zf + (size_t)s * EMB + kloc);
                    uint4 qb = *reinterpret_cast<const uint4*>(zf + (size_t)d * EMB + kloc);
                    float2 a0 = h2f2(qa.x), b0 = h2f2(qb.x);
                    float2 a1 = h2f2(qa.y), b1 = h2f2(qb.y);
                    float2 a2 = h2f2(qa.z), b2 = h2f2(qb.z);
                    float2 a3 = h2f2(qa.w), b3 = h2f2(qb.w);
                    uint4 o = make_uint4(pkh2(a0.x * b0.x, a0.y * b0.y),
                                         pkh2(a1.x * b1.x, a1.y * b1.y),
                                         pkh2(a2.x * b2.x, a2.y * b2.y),
                                         pkh2(a3.x * b3.x, a3.y * b3.y));
                    *reinterpret_cast<uint4*>(smem + (uint32_t)(ks & 1) * STAGE + ST_A + so) = o;
                }
            } else {
                int rowa = min(m0 + row, M - 1);
                cp16(base + ST_A + so, Ah_ + (size_t)rowa * KTOT + k0 + c * 8);
            }
        }
#pragma unroll
        for (int i = 0; i < 4; i++) {
            int id  = tid + i * 256;
            int row = id >> 3;
            int c   = id & 7;
            cp16(base + ST_WH + soffs(row, c),
                 Whi + (size_t)(n0 + row) * KTOT + k0 + c * 8);
        }
    };

    float acc[2][8][4];
#pragma unroll
    for (int a = 0; a < 2; a++)
#pragma unroll
        for (int b = 0; b < 8; b++)
#pragma unroll
            for (int c = 0; c < 4; c++) acc[a][b][c] = 0.f;

    const int lrow  = (lane & 7) + ((lane >> 3) & 1) * 8;
    const int khalf = lane >> 4;

    load_stage(0);
    CP_COMMIT();
    if (MODE == 4) __syncthreads();

    for (int ks = 0; ks < NS; ks++) {
        if (ks + 1 < NS) load_stage(ks + 1);
        CP_COMMIT();
        CP_WAIT1();
        __syncthreads();

        const uint32_t base = sb + (uint32_t)(ks & 1) * STAGE;
#pragma unroll
        for (int kk = 0; kk < 4; kk++) {
            const int c = kk * 2 + khalf;
            uint32_t ah[2][4];
#pragma unroll
            for (int mi = 0; mi < 2; mi++) {
                int row = wm * 32 + mi * 16 + lrow;
                ldsm4(ah[mi][0], ah[mi][1], ah[mi][2], ah[mi][3],
                      base + ST_A + soffs(row, c));
            }
            uint32_t bh[4][4];
#pragma unroll
            for (int ng = 0; ng < 4; ng++) {
                int row = wn * 64 + ng * 16 + lrow;
                ldsm4(bh[ng][0], bh[ng][1], bh[ng][2], bh[ng][3],
                      base + ST_WH + soffs(row, c));
            }
#pragma unroll
            for (int mi = 0; mi < 2; mi++)
#pragma unroll
                for (int ng = 0; ng < 4; ng++)
#pragma unroll
                    for (int sub = 0; sub < 2; sub++) {
                        int ni = ng * 2 + sub;
                        float* d = acc[mi][ni];
                        mma_h(d[0], d[1], d[2], d[3],
                              ah[mi][0], ah[mi][1], ah[mi][2], ah[mi][3],
                              bh[ng][sub], bh[ng][sub + 2]);
                    }
        }
        __syncthreads();
    }

    // ---- epilogue ----
    if (MODE == 4) {
#pragma unroll
        for (int mi = 0; mi < 2; mi++) {
            float s0 = 0.f, s1 = 0.f;
#pragma unroll
            for (int ni = 0; ni < 8; ni++) {
                int col = n0 + wn * 64 + ni * 8 + 2 * (lane & 3);
                float b0 = __ldg(bias + col),  b1 = __ldg(bias + col + 1);
                float w0 = __ldg(Wp2v + col),  w1 = __ldg(Wp2v + col + 1);
                s0 += fmaxf(acc[mi][ni][0] + b0, 0.f) * w0
                    + fmaxf(acc[mi][ni][1] + b1, 0.f) * w1;
                s1 += fmaxf(acc[mi][ni][2] + b0, 0.f) * w0
                    + fmaxf(acc[mi][ni][3] + b1, 0.f) * w1;
            }
            s0 += __shfl_xor_sync(0xffffffffu, s0, 1);
            s0 += __shfl_xor_sync(0xffffffffu, s0, 2);
            s1 += __shfl_xor_sync(0xffffffffu, s1, 1);
            s1 += __shfl_xor_sync(0xffffffffu, s1, 2);
            if ((lane & 3) == 0) {
                int r0 = m0 + wm * 32 + mi * 16 + (lane >> 2);
                int r1 = r0 + 8;
                if (r0 < M) atomicAdd(Cf + r0, s0);
                if (r1 < M) atomicAdd(Cf + r1, s1);
            }
        }
        return;
    }
#pragma unroll
    for (int mi = 0; mi < 2; mi++) {
        int r0 = m0 + wm * 32 + mi * 16 + (lane >> 2);
        int r1 = r0 + 8;
#pragma unroll
        for (int ni = 0; ni < 8; ni++) {
            int col = n0 + wn * 64 + ni * 8 + 2 * (lane & 3);
            float v0 = acc[mi][ni][0], v1 = acc[mi][ni][1];
            float v2 = acc[mi][ni][2], v3 = acc[mi][ni][3];
            if (MODE == 1) {
                float b0 = __ldg(bias + col), b1 = __ldg(bias + col + 1);
                v0 = fmaxf(v0 + b0, 0.f); v1 = fmaxf(v1 + b1, 0.f);
                v2 = fmaxf(v2 + b0, 0.f); v3 = fmaxf(v3 + b1, 0.f);
            }
            if (r0 < M)
                *reinterpret_cast<uint32_t*>(Ch + (size_t)r0 * NTOT + col) = pkh2(v0, v1);
            if (r1 < M)
                *reinterpret_cast<uint32_t*>(Ch + (size_t)r1 * NTOT + col) = pkh2(v2, v3);
        }
    }
}

// ===========================================================================
extern "C" void kernel_launch(void* const* d_in, const int* in_sizes, int n_in,
                              void* d_out, int out_size) {
    const int*   tids     = (const int*)  d_in[0];
    const int*   rows     = (const int*)  d_in[1];
    const int*   cols     = (const int*)  d_in[2];
    const float* vals     = (const float*)d_in[3];
    const int*   pairs    = (const int*)  d_in[4];
    const float* node_emb = (const float*)d_in[5];
    const float* type_emb = (const float*)d_in[6];
    const float* W1  = (const float*)d_in[7];
    const float* b1  = (const float*)d_in[8];
    const float* W2  = (const float*)d_in[9];
    const float* b2  = (const float*)d_in[10];
    const float* Wp1 = (const float*)d_in[11];
    const float* bp1 = (const float*)d_in[12];
    const float* Wp2 = (const float*)d_in[13];
    const float* bp2 = (const float*)d_in[14];
    float* out = (float*)d_out;

    void *pxh, *paxh, *phh, *phwh, *pzh;
    void *w1h, *w2h, *wp1h;
    cudaGetSymbolAddress(&pxh,  g_xh);
    cudaGetSymbolAddress(&paxh, g_axh);
    cudaGetSymbolAddress(&phh,  g_hh);
    cudaGetSymbolAddress(&phwh, g_hwh);
    cudaGetSymbolAddress(&pzh,  g_zh);
    cudaGetSymbolAddress(&w1h,  g_w1hi);
    cudaGetSymbolAddress(&w2h,  g_w2hi);
    cudaGetSymbolAddress(&wp1h, g_wp1hi);

    constexpr int SMEM = 2 * 32768;   // 64 KB
    cudaFuncSetAttribute(gemm_mma<256, 256, 1>,
                         cudaFuncAttributeMaxDynamicSharedMemorySize, SMEM);
    cudaFuncSetAttribute(gemm_mma<256, 128, 3>,
                         cudaFuncAttributeMaxDynamicSharedMemorySize, SMEM);
    cudaFuncSetAttribute(gemm_mma<384, 128, 4>,
                         cudaFuncAttributeMaxDynamicSharedMemorySize, SMEM);

    // 0. weight prep
    {
        int tot = HID * HID + HID * EMB + 3 * EMB * EMB;
        prep_w_all<<<(tot + 255) / 256, 256>>>(W1, W2, Wp1);
    }
    // 1. row_ptr
    build_rowptr<<<(N_EDGES + 255) / 256, 256>>>(rows);
    // 2. x = fp16(node_emb + type_emb[type])
    add_emb<<<(N_NODES * HID / 4 + 255) / 256, 256>>>(node_emb, type_emb, tids);
    // 3. ax = spmm(x) -> fp16
    spmm_warp<HID, 2><<<(N_NODES + 7) / 8, 256>>>(
        (const __half*)pxh, nullptr, (__half*)paxh, cols, vals, nullptr);
    // 4. h = relu(ax @ W1 + b1) -> fp16
    {
        dim3 grid((N_NODES + 127) / 128, HID / 128);
        gemm_mma<256, 256, 1><<<grid, 256, SMEM>>>(
            (const __half*)paxh, (const __half*)w1h,
            nullptr, (__half*)phh, b1, nullptr, nullptr, nullptr, N_NODES);
    }
    // 5. hw = h @ W2 -> fp16
    {
        dim3 grid((N_NODES + 127) / 128, EMB / 128);
        gemm_mma<256, 128, 3><<<grid, 256, SMEM>>>(
            (const __half*)phh, (const __half*)w2h,
            nullptr, (__half*)phwh, nullptr, nullptr, nullptr, nullptr, N_NODES);
    }
    // 6. z = fp16(spmm(hw) + b2)
    spmm_warp<EMB, 2><<<(N_NODES + 7) / 8, 256>>>(
        (const __half*)phwh, nullptr, (__half*)pzh, cols, vals, b2);
    // 7+8. out = relu(feat @ Wp1 + bp1) @ Wp2 + bp2  [fused feat + dot]
    init_out<<<(N_PAIRS + 255) / 256, 256>>>(out, bp2);
    {
        dim3 grid((N_PAIRS + 127) / 128, EMB / 128);
        gemm_mma<384, 128, 4><<<grid, 256, SMEM>>>(
            nullptr, (const __half*)wp1h,
            out, nullptr, bp1, Wp2, (const __half*)pzh, pairs, N_PAIRS);
    }
}

// round 17
// speedup vs baseline: 1.4599x; 1.0162x over previous
#include <cuda_runtime.h>
#include <cuda_fp16.h>
#include <cstdint>

#define N_NODES 100000
#define N_EDGES 3200000
#define HID 256
#define EMB 128
#define N_PAIRS 100000

// ===================== scratch (device globals) =============================
__device__ __half g_xh [N_NODES * HID];         // spmm1 input (fp16)
__device__ __half g_axh[N_NODES * HID];         // spmm1 out = GEMM1 A (fp16)
__device__ __half g_hh [N_NODES * HID];         // GEMM1 out = GEMM2 A (fp16)
__device__ __half g_hwh[N_NODES * EMB];         // GEMM2 out (fp16, feeds spmm2)
__device__ __half g_zh [N_NODES * EMB];         // spmm2 out (fp16, feeds GEMM3)
__device__ int    g_rowptr[N_NODES + 1];
// transposed fp16 weights: [N][K]
__device__ __half g_w1hi[HID * HID];
__device__ __half g_w2hi[EMB * HID];
__device__ __half g_wp1hi[EMB * 3 * EMB];

// ===================== helpers ==============================================
__device__ __forceinline__ uint32_t smem_u32(const void* p) {
    uint32_t a;
    asm("{ .reg .u64 t; cvta.to.shared.u64 t, %1; cvt.u32.u64 %0, t; }"
        : "=r"(a) : "l"(p));
    return a;
}
__device__ __forceinline__ void cp16(uint32_t dst, const void* src) {
    asm volatile("cp.async.cg.shared.global [%0], [%1], 16;" :: "r"(dst), "l"(src));
}
#define CP_COMMIT() asm volatile("cp.async.commit_group;" ::: "memory")
#define CP_WAIT1()  asm volatile("cp.async.wait_group 1;" ::: "memory")

__device__ __forceinline__ void ldsm4(uint32_t& r0, uint32_t& r1,
                                      uint32_t& r2, uint32_t& r3, uint32_t addr) {
    asm volatile("ldmatrix.sync.aligned.m8n8.x4.shared.b16 {%0,%1,%2,%3}, [%4];"
                 : "=r"(r0), "=r"(r1), "=r"(r2), "=r"(r3) : "r"(addr));
}
__device__ __forceinline__ void mma_h(float& d0, float& d1, float& d2, float& d3,
                                      uint32_t a0, uint32_t a1, uint32_t a2, uint32_t a3,
                                      uint32_t b0, uint32_t b1) {
    asm volatile(
        "mma.sync.aligned.m16n8k16.row.col.f32.f16.f16.f32 "
        "{%0,%1,%2,%3}, {%4,%5,%6,%7}, {%8,%9}, {%0,%1,%2,%3};"
        : "+f"(d0), "+f"(d1), "+f"(d2), "+f"(d3)
        : "r"(a0), "r"(a1), "r"(a2), "r"(a3), "r"(b0), "r"(b1));
}
__device__ __forceinline__ float2 h2f2(uint32_t u) {
    return __half22float2(*reinterpret_cast<__half2*>(&u));
}
__device__ __forceinline__ uint32_t pkh2(float a, float b) {
    __half2 t = __floats2half2_rn(a, b);
    return *reinterpret_cast<uint32_t*>(&t);
}

// ===================== fused setup kernel ====================================
// Block ranges (all jobs independent, run concurrently):
//   [0, RB1): rowptr scatter        (N_EDGES threads)
//   [RB1, RB2): add_emb             (N_NODES*HID/4 float4)
//   [RB2, RB3): prep_w              (W1,W2,Wp1 -> transposed fp16)
//   [RB3, RB4): init_out            (out[p] = bp2)
#define RB1 ((N_EDGES + 255) / 256)                          // 12500
#define RB2 (RB1 + (N_NODES * HID / 4 + 255) / 256)          // +25000
#define NWTOT (HID * HID + HID * EMB + 3 * EMB * EMB)        // 147456
#define RB3 (RB2 + (NWTOT + 255) / 256)                      // +576
#define RB4 (RB3 + (N_PAIRS + 255) / 256)                    // +391

__global__ void setup_all(const int* __restrict__ rows,
                          const float* __restrict__ node_emb,
                          const float* __restrict__ type_emb,
                          const int* __restrict__ tids,
                          const float* __restrict__ W1,
                          const float* __restrict__ W2,
                          const float* __restrict__ Wp1,
                          const float* __restrict__ bp2,
                          float* __restrict__ out) {
    int b = blockIdx.x;
    if (b < RB1) {
        // ---- rowptr ----
        int e = b * 256 + threadIdx.x;
        if (e >= N_EDGES) return;
        int r  = rows[e];
        int rn = (e + 1 < N_EDGES) ? rows[e + 1] : N_NODES;
        if (e == 0)
            for (int n = 0; n <= r; n++) g_rowptr[n] = 0;
        for (int n = r + 1; n <= rn; n++) g_rowptr[n] = e + 1;
    } else if (b < RB2) {
        // ---- add_emb ----
        int i = (b - RB1) * 256 + threadIdx.x;
        const int NV = N_NODES * HID / 4;
        if (i >= NV) return;
        int n  = i / (HID / 4);
        int k4 = i % (HID / 4);
        int t  = tids[n];
        float4 a = reinterpret_cast<const float4*>(node_emb)[i];
        float4 bb = reinterpret_cast<const float4*>(type_emb)[t * (HID / 4) + k4];
        reinterpret_cast<uint2*>(g_xh)[i] =
            make_uint2(pkh2(a.x + bb.x, a.y + bb.y), pkh2(a.z + bb.z, a.w + bb.w));
    } else if (b < RB3) {
        // ---- prep_w ----
        int i = (b - RB2) * 256 + threadIdx.x;
        const int S1 = HID * HID;
        const int S2 = S1 + HID * EMB;
        const int S3 = S2 + 3 * EMB * EMB;
        if (i < S1) {
            int k = i / HID, n = i % HID;
            g_w1hi[n * HID + k] = __float2half(W1[i]);
        } else if (i < S2) {
            int j = i - S1;
            int k = j / EMB, n = j % EMB;
            g_w2hi[n * HID + k] = __float2half(W2[j]);
        } else if (i < S3) {
            int j = i - S2;
            int k = j / EMB, n = j % EMB;
            g_wp1hi[n * (3 * EMB) + k] = __float2half(Wp1[j]);
        }
    } else {
        // ---- init_out ----
        int i = (b - RB3) * 256 + threadIdx.x;
        if (i < N_PAIRS) out[i] = bp2[0];
    }
}

// ---------------- SpMM: warp-per-node (round-10 structure, FROZEN) ----------
// OUT: 0 = fp32 (+bias), 2 = fp16 (+bias added in fp32 before rounding).
template <int H, int OUT>
__global__ void __launch_bounds__(256, 6)
spmm_warp(const __half* __restrict__ x,
          float* __restrict__ yf,
          __half* __restrict__ yh,
          const int* __restrict__ cols,
          const float* __restrict__ vals,
          const float* __restrict__ bias) {
    constexpr int PER = H / 32;
    constexpr int UNR = (PER == 8) ? 4 : 8;
    const int lane = threadIdx.x & 31;
    const int n = blockIdx.x * 8 + (threadIdx.x >> 5);
    if (n >= N_NODES) return;

    int e  = g_rowptr[n];
    const int e1 = g_rowptr[n + 1];

    float acc[PER];
#pragma unroll
    for (int k = 0; k < PER; k++) acc[k] = 0.f;

    for (; e + 32 <= e1; e += 32) {
        int   c = __ldg(cols + e + lane);
        float v = __ldg(vals + e + lane);
#pragma unroll UNR
        for (int j = 0; j < 32; j++) {
            int   cj = __shfl_sync(0xffffffffu, c, j);
            float vj = __shfl_sync(0xffffffffu, v, j);
            if (PER == 8) {
                uint4 q = __ldg(reinterpret_cast<const uint4*>(x) +
                                (size_t)cj * (H / 8) + lane);
                float2 f0 = h2f2(q.x), f1 = h2f2(q.y), f2 = h2f2(q.z), f3 = h2f2(q.w);
                acc[0] += vj * f0.x; acc[1] += vj * f0.y;
                acc[2] += vj * f1.x; acc[3] += vj * f1.y;
                acc[4 % PER] += vj * f2.x; acc[5 % PER] += vj * f2.y;
                acc[6 % PER] += vj * f3.x; acc[7 % PER] += vj * f3.y;
            } else {
                uint2 q = __ldg(reinterpret_cast<const uint2*>(x) +
                                (size_t)cj * (H / 4) + lane);
                float2 f0 = h2f2(q.x), f1 = h2f2(q.y);
                acc[0] += vj * f0.x; acc[1] += vj * f0.y;
                acc[2 % PER] += vj * f1.x; acc[3 % PER] += vj * f1.y;
            }
        }
    }
    int rem = e1 - e;
    if (rem > 0) {
        int   c = (lane < rem) ? __ldg(cols + e + lane) : 0;
        float v = (lane < rem) ? __ldg(vals + e + lane) : 0.f;
        for (int j = 0; j < rem; j++) {
            int   cj = __shfl_sync(0xffffffffu, c, j);
            float vj = __shfl_sync(0xffffffffu, v, j);
            if (PER == 8) {
                uint4 q = __ldg(reinterpret_cast<const uint4*>(x) +
                                (size_t)cj * (H / 8) + lane);
                float2 f0 = h2f2(q.x), f1 = h2f2(q.y), f2 = h2f2(q.z), f3 = h2f2(q.w);
                acc[0] += vj * f0.x; acc[1] += vj * f0.y;
                acc[2] += vj * f1.x; acc[3] += vj * f1.y;
                acc[4 % PER] += vj * f2.x; acc[5 % PER] += vj * f2.y;
                acc[6 % PER] += vj * f3.x; acc[7 % PER] += vj * f3.y;
            } else {
                uint2 q = __ldg(reinterpret_cast<const uint2*>(x) +
                                (size_t)cj * (H / 4) + lane);
                float2 f0 = h2f2(q.x), f1 = h2f2(q.y);
                acc[0] += vj * f0.x; acc[1] += vj * f0.y;
                acc[2 % PER] += vj * f1.x; acc[3 % PER] += vj * f1.y;
            }
        }
    }

    if (OUT == 0) {
#pragma unroll
        for (int k = 0; k < PER; k++)
            if (bias) acc[k] += __ldg(bias + lane * PER + k);
#pragma unroll
        for (int k = 0; k < PER; k += 4) {
            float4 o = make_float4(acc[k], acc[k + 1],
                                   acc[(k + 2) % PER], acc[(k + 3) % PER]);
            *reinterpret_cast<float4*>(yf + (size_t)n * H + lane * PER + k) = o;
        }
    } else {
        if (bias) {
#pragma unroll
            for (int k = 0; k < PER; k++)
                acc[k] += __ldg(bias + lane * PER + k);
        }
        uint32_t p[PER / 2];
#pragma unroll
        for (int k = 0; k < PER / 2; k++)
            p[k] = pkh2(acc[2 * k], acc[2 * k + 1]);
        if (PER == 8) {
            uint4 o = make_uint4(p[0], p[1], p[2 % (PER / 2)], p[3 % (PER / 2)]);
            *reinterpret_cast<uint4*>(yh + (size_t)n * H + lane * 8) = o;
        } else {
            uint2 o = make_uint2(p[0], p[1 % (PER / 2)]);
            *reinterpret_cast<uint2*>(yh + (size_t)n * H + lane * 4) = o;
        }
    }
}

// ===================== HMMA GEMM (fp16, 1-product) ==========================
// C[M, NTOT] = A[M, KTOT] @ W^T.  CTA 128x128, 8 warps 4x2, warp tile 32x64,
// KC=64, 2-stage cp.async.
// MODE 1: bias+relu fp16 out.  MODE 3: fp16 out.
// MODE 4: fused feat from fp16 z via pairs; bias+relu, dot Wp2v,
//         atomicAdd into Cf (pre-initialized with bp2).
template <int KTOT, int NTOT, int MODE>
__global__ void __launch_bounds__(256, 2)
gemm_mma(const __half* __restrict__ Ah_,
         const __half* __restrict__ Whi,
         float* __restrict__ Cf,
         __half* __restrict__ Ch,
         const float* __restrict__ bias,
         const float* __restrict__ Wp2v,
         const __half* __restrict__ zf,
         const int* __restrict__ pairs, int M) {
    constexpr int KC = 64;
    constexpr int NS = KTOT / KC;
    constexpr int ST_A  = 0;
    constexpr int ST_WH = 16384;
    constexpr int STAGE = 32768;

    extern __shared__ __align__(128) char smem[];
    const uint32_t sb = smem_u32(smem);

    const int tid  = threadIdx.x;
    const int lane = tid & 31;
    const int wm   = (tid >> 5) & 3;
    const int wn   = tid >> 7;
    const int m0   = blockIdx.x * 128;
    const int n0   = blockIdx.y * 128;

    auto soffs = [](int row, int c) -> uint32_t {
        return (uint32_t)(row * 128 + ((c ^ (row & 7)) << 4));
    };

    auto load_stage = [&](int ks) {
        const int k0 = ks * KC;
        const uint32_t base = sb + (uint32_t)(ks & 1) * STAGE;
#pragma unroll
        for (int i = 0; i < 4; i++) {
            int id  = tid + i * 256;
            int row = id >> 3;
            int c   = id & 7;
            uint32_t so = soffs(row, c);
            if (MODE == 4) {
                int p = min(m0 + row, M - 1);
                int kcol = k0 + c * 8;
                int seg  = kcol >> 7;
                int kloc = kcol & 127;
                int s = __ldg(pairs + p);
                int d = __ldg(pairs + N_PAIRS + p);
                if (seg == 0) {
                    cp16(base + ST_A + so, zf + (size_t)s * EMB + kloc);
                } else if (seg == 1) {
                    cp16(base + ST_A + so, zf + (size_t)d * EMB + kloc);
                } else {
                    uint4 qa = *reinterpret_cast<const uint4*>(zf + (size_t)s * EMB + kloc);
                    uint4 qb = *reinterpret_cast<const uint4*>(zf + (size_t)d * EMB + kloc);
                    float2 a0 = h2f2(qa.x), b0 = h2f2(qb.x);
                    float2 a1 = h2f2(qa.y), b1 = h2f2(qb.y);
                    float2 a2 = h2f2(qa.z), b2 = h2f2(qb.z);
                    float2 a3 = h2f2(qa.w), b3 = h2f2(qb.w);
                    uint4 o = make_uint4(pkh2(a0.x * b0.x, a0.y * b0.y),
                                         pkh2(a1.x * b1.x, a1.y * b1.y),
                                         pkh2(a2.x * b2.x, a2.y * b2.y),
                                         pkh2(a3.x * b3.x, a3.y * b3.y));
                    *reinterpret_cast<uint4*>(smem + (uint32_t)(ks & 1) * STAGE + ST_A + so) = o;
                }
            } else {
                int rowa = min(m0 + row, M - 1);
                cp16(base + ST_A + so, Ah_ + (size_t)rowa * KTOT + k0 + c * 8);
            }
        }
#pragma unroll
        for (int i = 0; i < 4; i++) {
            int id  = tid + i * 256;
            int row = id >> 3;
            int c   = id & 7;
            cp16(base + ST_WH + soffs(row, c),
                 Whi + (size_t)(n0 + row) * KTOT + k0 + c * 8);
        }
    };

    float acc[2][8][4];
#pragma unroll
    for (int a = 0; a < 2; a++)
#pragma unroll
        for (int b = 0; b < 8; b++)
#pragma unroll
            for (int c = 0; c < 4; c++) acc[a][b][c] = 0.f;

    const int lrow  = (lane & 7) + ((lane >> 3) & 1) * 8;
    const int khalf = lane >> 4;

    load_stage(0);
    CP_COMMIT();
    if (MODE == 4) __syncthreads();

    for (int ks = 0; ks < NS; ks++) {
        if (ks + 1 < NS) load_stage(ks + 1);
        CP_COMMIT();
        CP_WAIT1();
        __syncthreads();

        const uint32_t base = sb + (uint32_t)(ks & 1) * STAGE;
#pragma unroll
        for (int kk = 0; kk < 4; kk++) {
            const int c = kk * 2 + khalf;
            uint32_t ah[2][4];
#pragma unroll
            for (int mi = 0; mi < 2; mi++) {
                int row = wm * 32 + mi * 16 + lrow;
                ldsm4(ah[mi][0], ah[mi][1], ah[mi][2], ah[mi][3],
                      base + ST_A + soffs(row, c));
            }
            uint32_t bh[4][4];
#pragma unroll
            for (int ng = 0; ng < 4; ng++) {
                int row = wn * 64 + ng * 16 + lrow;
                ldsm4(bh[ng][0], bh[ng][1], bh[ng][2], bh[ng][3],
                      base + ST_WH + soffs(row, c));
            }
#pragma unroll
            for (int mi = 0; mi < 2; mi++)
#pragma unroll
                for (int ng = 0; ng < 4; ng++)
#pragma unroll
                    for (int sub = 0; sub < 2; sub++) {
                        int ni = ng * 2 + sub;
                        float* d = acc[mi][ni];
                        mma_h(d[0], d[1], d[2], d[3],
                              ah[mi][0], ah[mi][1], ah[mi][2], ah[mi][3],
                              bh[ng][sub], bh[ng][sub + 2]);
                    }
        }
        __syncthreads();
    }

    // ---- epilogue ----
    if (MODE == 4) {
#pragma unroll
        for (int mi = 0; mi < 2; mi++) {
            float s0 = 0.f, s1 = 0.f;
#pragma unroll
            for (int ni = 0; ni < 8; ni++) {
                int col = n0 + wn * 64 + ni * 8 + 2 * (lane & 3);
                float b0 = __ldg(bias + col),  b1 = __ldg(bias + col + 1);
                float w0 = __ldg(Wp2v + col),  w1 = __ldg(Wp2v + col + 1);
                s0 += fmaxf(acc[mi][ni][0] + b0, 0.f) * w0
                    + fmaxf(acc[mi][ni][1] + b1, 0.f) * w1;
                s1 += fmaxf(acc[mi][ni][2] + b0, 0.f) * w0
                    + fmaxf(acc[mi][ni][3] + b1, 0.f) * w1;
            }
            s0 += __shfl_xor_sync(0xffffffffu, s0, 1);
            s0 += __shfl_xor_sync(0xffffffffu, s0, 2);
            s1 += __shfl_xor_sync(0xffffffffu, s1, 1);
            s1 += __shfl_xor_sync(0xffffffffu, s1, 2);
            if ((lane & 3) == 0) {
                int r0 = m0 + wm * 32 + mi * 16 + (lane >> 2);
                int r1 = r0 + 8;
                if (r0 < M) atomicAdd(Cf + r0, s0);
                if (r1 < M) atomicAdd(Cf + r1, s1);
            }
        }
        return;
    }
#pragma unroll
    for (int mi = 0; mi < 2; mi++) {
        int r0 = m0 + wm * 32 + mi * 16 + (lane >> 2);
        int r1 = r0 + 8;
#pragma unroll
        for (int ni = 0; ni < 8; ni++) {
            int col = n0 + wn * 64 + ni * 8 + 2 * (lane & 3);
            float v0 = acc[mi][ni][0], v1 = acc[mi][ni][1];
            float v2 = acc[mi][ni][2], v3 = acc[mi][ni][3];
            if (MODE == 1) {
                float b0 = __ldg(bias + col), b1 = __ldg(bias + col + 1);
                v0 = fmaxf(v0 + b0, 0.f); v1 = fmaxf(v1 + b1, 0.f);
                v2 = fmaxf(v2 + b0, 0.f); v3 = fmaxf(v3 + b1, 0.f);
            }
            if (r0 < M)
                *reinterpret_cast<uint32_t*>(Ch + (size_t)r0 * NTOT + col) = pkh2(v0, v1);
            if (r1 < M)
                *reinterpret_cast<uint32_t*>(Ch + (size_t)r1 * NTOT + col) = pkh2(v2, v3);
        }
    }
}

// ===========================================================================
extern "C" void kernel_launch(void* const* d_in, const int* in_sizes, int n_in,
                              void* d_out, int out_size) {
    const int*   tids     = (const int*)  d_in[0];
    const int*   rows     = (const int*)  d_in[1];
    const int*   cols     = (const int*)  d_in[2];
    const float* vals     = (const float*)d_in[3];
    const int*   pairs    = (const int*)  d_in[4];
    const float* node_emb = (const float*)d_in[5];
    const float* type_emb = (const float*)d_in[6];
    const float* W1  = (const float*)d_in[7];
    const float* b1  = (const float*)d_in[8];
    const float* W2  = (const float*)d_in[9];
    const float* b2  = (const float*)d_in[10];
    const float* Wp1 = (const float*)d_in[11];
    const float* bp1 = (const float*)d_in[12];
    const float* Wp2 = (const float*)d_in[13];
    const float* bp2 = (const float*)d_in[14];
    float* out = (float*)d_out;

    void *pxh, *paxh, *phh, *phwh, *pzh;
    void *w1h, *w2h, *wp1h;
    cudaGetSymbolAddress(&pxh,  g_xh);
    cudaGetSymbolAddress(&paxh, g_axh);
    cudaGetSymbolAddress(&phh,  g_hh);
    cudaGetSymbolAddress(&phwh, g_hwh);
    cudaGetSymbolAddress(&pzh,  g_zh);
    cudaGetSymbolAddress(&w1h,  g_w1hi);
    cudaGetSymbolAddress(&w2h,  g_w2hi);
    cudaGetSymbolAddress(&wp1h, g_wp1hi);

    constexpr int SMEM = 2 * 32768;   // 64 KB
    cudaFuncSetAttribute(gemm_mma<256, 256, 1>,
                         cudaFuncAttributeMaxDynamicSharedMemorySize, SMEM);
    cudaFuncSetAttribute(gemm_mma<256, 128, 3>,
                         cudaFuncAttributeMaxDynamicSharedMemorySize, SMEM);
    cudaFuncSetAttribute(gemm_mma<384, 128, 4>,
                         cudaFuncAttributeMaxDynamicSharedMemorySize, SMEM);

    // 0. fused setup: rowptr + add_emb + prep_w + init_out (one launch)
    setup_all<<<RB4, 256>>>(rows, node_emb, type_emb, tids, W1, W2, Wp1, bp2, out);
    // 1. ax = spmm(x) -> fp16
    spmm_warp<HID, 2><<<(N_NODES + 7) / 8, 256>>>(
        (const __half*)pxh, nullptr, (__half*)paxh, cols, vals, nullptr);
    // 2. h = relu(ax @ W1 + b1) -> fp16
    {
        dim3 grid((N_NODES + 127) / 128, HID / 128);
        gemm_mma<256, 256, 1><<<grid, 256, SMEM>>>(
            (const __half*)paxh, (const __half*)w1h,
            nullptr, (__half*)phh, b1, nullptr, nullptr, nullptr, N_NODES);
    }
    // 3. hw = h @ W2 -> fp16
    {
        dim3 grid((N_NODES + 127) / 128, EMB / 128);
        gemm_mma<256, 128, 3><<<grid, 256, SMEM>>>(
            (const __half*)phh, (const __half*)w2h,
            nullptr, (__half*)phwh, nullptr, nullptr, nullptr, nullptr, N_NODES);
    }
    // 4. z = fp16(spmm(hw) + b2)
    spmm_warp<EMB, 2><<<(N_NODES + 7) / 8, 256>>>(
        (const __half*)phwh, nullptr, (__half*)pzh, cols, vals, b2);
    // 5. out = relu(feat @ Wp1 + bp1) @ Wp2 + bp2  [fused feat + dot]
    {
        dim3 grid((N_PAIRS + 127) / 128, EMB / 128);
        gemm_mma<384, 128, 4><<<grid, 256, SMEM>>>(
            nullptr, (const __half*)wp1h,
            out, nullptr, bp1, Wp2, (const __half*)pzh, pairs, N_PAIRS);
    }
}